// round 2
// baseline (speedup 1.0000x reference)
#include <cuda_runtime.h>
#include <math.h>

#define NN   20000
#define FF   64
#define EE   320000
#define GG   20
#define NGG  1000
#define NELS 10
#define NBB  8
#define RMAXF 5.0f
#define HML  16

// output layout (float32, 20160 elems):
#define OUT_TE      0        // [20]  total_energy
#define OUT_NE      20       // [20000] node_energy
#define OUT_CONTRIB 20020    // [20,3] contributions
#define OUT_POL     20080    // [20,3] pol
#define OUT_TC      20140    // [20]  total_charge
#define OUT_TOTAL   20160

// ---------------- device scratch (no allocation allowed) ----------------
__device__ float g_sc[NN * FF];     // current node scalars
__device__ float g_agg[NN * FF];    // per-layer aggregation (s=0 only!)
__device__ float g_ef[EE * NBB];    // compacted active-edge radial features
__device__ int   g_asnd[EE];
__device__ int   g_arcv[EE];
__device__ float g_cd[NN];          // charge density
__device__ int   g_count;           // active edge count

// ---------------- K0: zero everything that accumulates ----------------
__global__ void k_zero(float* __restrict__ out) {
    int i = blockIdx.x * blockDim.x + threadIdx.x;
    if (i < NN * FF) g_agg[i] = 0.0f;
    if (i < OUT_TOTAL) out[i] = 0.0f;
    if (i == 0) g_count = 0;
}

// ---------------- K1: node init (embed, E0, FQ, pol node part) ----------------
__global__ void k_node_init(const float* __restrict__ attrs,
                            const float* __restrict__ pos,
                            const int*   __restrict__ batch,
                            const float* __restrict__ ae,
                            const float* __restrict__ embw,
                            const float* __restrict__ fc,
                            float* __restrict__ out) {
    int n = blockIdx.x;
    int f = threadIdx.x;
    __shared__ float at[NELS];
    __shared__ float fq_s;
    if (f < NELS) at[f] = attrs[n * NELS + f];
    __syncthreads();
    float s = 0.0f;
#pragma unroll
    for (int k = 0; k < NELS; k++) s = fmaf(at[k], embw[k * FF + f], s);
    g_sc[n * FF + f] = s;
    if (f == 0) {
        float fq = 0.0f, ne0 = 0.0f;
#pragma unroll
        for (int k = 0; k < NELS; k++) { fq = fmaf(at[k], fc[k], fq); ne0 = fmaf(at[k], ae[k], ne0); }
        g_cd[n] = fq;
        out[OUT_NE + n] = ne0;
        int g = batch[n];
        atomicAdd(&out[OUT_CONTRIB + g * 3 + 0], ne0);
        fq_s = fq;
    }
    __syncthreads();
    if (f < 3) {
        int g = batch[n];
        atomicAdd(&out[OUT_POL + g * 3 + f], fq_s * pos[n * 3 + f]);
    }
}

// ---------------- K2: edge geometry + radial basis + flux/pol + compaction ----
// Warp-aggregated compaction: one atomicAdd(&g_count) per warp instead of per
// active edge (the single-address L2 atomic ALU serializes per op otherwise).
__global__ void k_edge_geom(const float* __restrict__ pos,
                            const int*   __restrict__ ei,
                            const int*   __restrict__ batch,
                            const float* __restrict__ fw,   // flux_w [2,8]
                            float* __restrict__ out) {
    int e = blockIdx.x * blockDim.x + threadIdx.x;   // EE divisible by 32: full warps
    int lane = threadIdx.x & 31;

    bool active = false;
    int snd = 0, rcv = 0;
    float dx = 0, dy = 0, dz = 0, flux = 0;
    float ef[NBB];

    if (e < EE) {
        snd = ei[e]; rcv = ei[EE + e];
        dx = pos[rcv * 3 + 0] - pos[snd * 3 + 0];
        dy = pos[rcv * 3 + 1] - pos[snd * 3 + 1];
        dz = pos[rcv * 3 + 2] - pos[snd * 3 + 2];
        float r = sqrtf(fmaf(dx, dx, fmaf(dy, dy, dz * dz)) + 1e-12f);
        if (r < RMAXF) {
            active = true;
            float x = r * (1.0f / RMAXF);
            float x2 = x * x;
            float x5 = x2 * x2 * x;
            float u = 1.0f + x5 * (-21.0f + x * (35.0f - 15.0f * x));
            float pref = 0.6324555320336759f * u / r;     // sqrt(2/5) * u / r
            float s1, c1;
            sincosf(r * 0.6283185307179586f, &s1, &c1);   // pi/5 * r
            float sn = s1, cn = c1;
#pragma unroll
            for (int i = 0; i < NBB; i++) {
                float v = pref * sn;
                ef[i] = v;
                flux = fmaf(v, fw[i] + fw[NBB + i], flux);
                float sn2 = sn * c1 + cn * s1;
                cn = cn * c1 - sn * s1;
                sn = sn2;
            }
        }
    }

    unsigned mask = __ballot_sync(0xffffffffu, active);
    if (mask) {
        int leader = __ffs(mask) - 1;
        int cnt = __popc(mask);
        int base = 0;
        if (lane == leader) base = atomicAdd(&g_count, cnt);
        base = __shfl_sync(0xffffffffu, base, leader);
        if (active) {
            int slot = base + __popc(mask & ((1u << lane) - 1u));
            float4* ef4 = (float4*)&g_ef[slot * NBB];
            ef4[0] = make_float4(ef[0], ef[1], ef[2], ef[3]);
            ef4[1] = make_float4(ef[4], ef[5], ef[6], ef[7]);
            g_asnd[slot] = snd;
            g_arcv[slot] = rcv;
            int g = batch[rcv];
            atomicAdd(&out[OUT_POL + g * 3 + 0], flux * dx);
            atomicAdd(&out[OUT_POL + g * 3 + 1], flux * dy);
            atomicAdd(&out[OUT_POL + g * 3 + 2], flux * dz);
        }
    }
}

// ---------------- K4: per-edge radial MLP + message scatter (s=0 only) -------
// 4 groups of 64 f-threads; each group processes 4 edges per iteration with
// 4 independent FMA accumulator chains sharing the register-resident W2 column.
__global__ void __launch_bounds__(256, 2)
k_edge_mlp(const float* __restrict__ W1,   // [8,64]
           const float* __restrict__ B1,   // [64]
           const float* __restrict__ W2) { // [64,64]
    int f = threadIdx.x & 63;
    int grp = threadIdx.x >> 6;
    float w1r[NBB];
#pragma unroll
    for (int i = 0; i < NBB; i++) w1r[i] = W1[i * FF + f];
    float b1r = B1[f];
    float4 w2c4[16];
#pragma unroll
    for (int j4 = 0; j4 < 16; j4++)
        w2c4[j4] = make_float4(W2[(j4 * 4 + 0) * FF + f], W2[(j4 * 4 + 1) * FF + f],
                               W2[(j4 * 4 + 2) * FF + f], W2[(j4 * 4 + 3) * FF + f]);

    __shared__ float hsm[4][4][FF];   // [group][edge][hidden]

    int count = g_count;
    int stride = gridDim.x * 16;
    int trips = (count + stride - 1) / stride;
    for (int t = 0; t < trips; t++) {
        int base = (t * gridDim.x + blockIdx.x) * 16 + grp * 4;
        // phase 1: hidden activations for 4 edges (thread f computes h_f)
#pragma unroll
        for (int e = 0; e < 4; e++) {
            int slot = base + e;
            float h = 0.0f;
            if (slot < count) {
                const float4* ef4 = (const float4*)&g_ef[slot * NBB];
                float4 a = __ldg(ef4), b = __ldg(ef4 + 1);
                float acc = b1r;
                acc = fmaf(a.x, w1r[0], acc); acc = fmaf(a.y, w1r[1], acc);
                acc = fmaf(a.z, w1r[2], acc); acc = fmaf(a.w, w1r[3], acc);
                acc = fmaf(b.x, w1r[4], acc); acc = fmaf(b.y, w1r[5], acc);
                acc = fmaf(b.z, w1r[6], acc); acc = fmaf(b.w, w1r[7], acc);
                h = acc / (1.0f + __expf(-acc));     // silu
            }
            hsm[grp][e][f] = h;
        }
        __syncthreads();
        // phase 2: R[e] = sum_j h[e][j] * W2[j][f], 4 independent chains
        float R0 = 0.0f, R1 = 0.0f, R2 = 0.0f, R3 = 0.0f;
        const float4* h0 = (const float4*)&hsm[grp][0][0];
        const float4* h1 = (const float4*)&hsm[grp][1][0];
        const float4* h2 = (const float4*)&hsm[grp][2][0];
        const float4* h3 = (const float4*)&hsm[grp][3][0];
#pragma unroll
        for (int j4 = 0; j4 < 16; j4++) {
            float4 w = w2c4[j4];
            float4 a = h0[j4];
            R0 = fmaf(a.x, w.x, R0); R0 = fmaf(a.y, w.y, R0);
            R0 = fmaf(a.z, w.z, R0); R0 = fmaf(a.w, w.w, R0);
            float4 b = h1[j4];
            R1 = fmaf(b.x, w.x, R1); R1 = fmaf(b.y, w.y, R1);
            R1 = fmaf(b.z, w.z, R1); R1 = fmaf(b.w, w.w, R1);
            float4 c = h2[j4];
            R2 = fmaf(c.x, w.x, R2); R2 = fmaf(c.y, w.y, R2);
            R2 = fmaf(c.z, w.z, R2); R2 = fmaf(c.w, w.w, R2);
            float4 d = h3[j4];
            R3 = fmaf(d.x, w.x, R3); R3 = fmaf(d.y, w.y, R3);
            R3 = fmaf(d.z, w.z, R3); R3 = fmaf(d.w, w.w, R3);
        }
        float Rv[4] = {R0, R1, R2, R3};
#pragma unroll
        for (int e = 0; e < 4; e++) {
            int slot = base + e;
            if (slot < count) {
                int snd = __ldg(&g_asnd[slot]);
                int rcv = __ldg(&g_arcv[slot]);
                float msg = Rv[e] * __ldg(&g_sc[snd * FF + f]);
                atomicAdd(&g_agg[rcv * FF + f], msg);
            }
        }
        __syncthreads();
    }
}

// ---------------- K5: node update (product+skip, readout, charge) ----------------
__global__ void k_node_update(const float* __restrict__ attrs,
                              const int*   __restrict__ batch,
                              const float* __restrict__ PW,    // prod_w[l]  [10,64]
                              const float* __restrict__ CW,    // charge_w[l][64]
                              const float* __restrict__ ROW,   // readout_w[l][64] (l==0)
                              const float* __restrict__ RW1,   // ro2_w1 [64,16]
                              const float* __restrict__ RB1,   // ro2_b1 [16]
                              const float* __restrict__ RW2,   // ro2_w2 [16]
                              float* __restrict__ out,
                              int last, int cidx) {
    int n = blockIdx.x;
    int f = threadIdx.x;
    __shared__ float at[NELS];
    __shared__ float scsm[FF];
    __shared__ float red[FF];
    __shared__ float res_c, res_e;
    if (f < NELS) at[f] = attrs[n * NELS + f];
    __syncthreads();
    float a = g_agg[n * FF + f] * 0.0625f;   // / AVG_NEIGH
    g_agg[n * FF + f] = 0.0f;                // pre-zero for next layer
    float pw = 0.0f;
#pragma unroll
    for (int k = 0; k < NELS; k++) pw = fmaf(at[k], PW[k * FF + f], pw);
    float sco = g_sc[n * FF + f];
    float sc = fmaf(a, a, a) + sco * pw;
    g_sc[n * FF + f] = sc;
    scsm[f] = sc;

    // --- reduce charge contribution ---
    red[f] = sc * CW[f];
    __syncthreads();
    if (f < 32) {
        float v = red[f] + red[f + 32];
        v += __shfl_down_sync(0xffffffffu, v, 16);
        v += __shfl_down_sync(0xffffffffu, v, 8);
        v += __shfl_down_sync(0xffffffffu, v, 4);
        v += __shfl_down_sync(0xffffffffu, v, 2);
        v += __shfl_down_sync(0xffffffffu, v, 1);
        if (f == 0) res_c = v;
    }
    __syncthreads();

    // --- node energy ---
    if (!last) {
        red[f] = sc * ROW[f];
        __syncthreads();
        if (f < 32) {
            float v = red[f] + red[f + 32];
            v += __shfl_down_sync(0xffffffffu, v, 16);
            v += __shfl_down_sync(0xffffffffu, v, 8);
            v += __shfl_down_sync(0xffffffffu, v, 4);
            v += __shfl_down_sync(0xffffffffu, v, 2);
            v += __shfl_down_sync(0xffffffffu, v, 1);
            if (f == 0) res_e = v;
        }
        __syncthreads();
    } else {
        if (f < HML) {
            float acc = RB1[f];
#pragma unroll
            for (int j = 0; j < FF; j++) acc = fmaf(scsm[j], RW1[j * HML + f], acc);
            float hv = acc / (1.0f + __expf(-acc));
            red[f] = hv * RW2[f];
        }
        __syncthreads();
        if (f == 0) {
            float v = 0.0f;
#pragma unroll
            for (int m = 0; m < HML; m++) v += red[m];
            res_e = v;
        }
        __syncthreads();
    }

    if (f == 0) {
        g_cd[n] += res_c;
        out[OUT_NE + n] += res_e;
        int g = batch[n];
        atomicAdd(&out[OUT_CONTRIB + g * 3 + cidx], res_e);
    }
}

// ---------------- K6: screened Coulomb per graph ----------------
// 16 i-partitions x 4 j-chunks: 320 blocks x 256 threads; each thread does
// 250 inner iterations -> 4x shorter dependent chains, 2x warps/SM.
__global__ void k_coulomb(const float* __restrict__ pos, float* __restrict__ out) {
    int g = blockIdx.x >> 4;          // 16 blocks per graph
    int ipart = blockIdx.x & 15;
    __shared__ float qs[NGG], px[NGG], py[NGG], pz[NGG];
    int base = g * NGG;
    for (int j = threadIdx.x; j < NGG; j += 256) {
        qs[j] = g_cd[base + j];
        px[j] = pos[(base + j) * 3 + 0];
        py[j] = pos[(base + j) * 3 + 1];
        pz[j] = pos[(base + j) * 3 + 2];
    }
    __syncthreads();
    int il = ipart * 64 + (threadIdx.x & 63);
    int jc = threadIdx.x >> 6;        // 0..3
    float e = 0.0f;
    if (il < NGG) {
        float xi = px[il], yi = py[il], zi = pz[il], qi = qs[il];
        float acc = 0.0f;
        for (int j = jc; j < NGG; j += 4) {
            float dx = xi - px[j], dy = yi - py[j], dz = zi - pz[j];
            float r = sqrtf(fmaf(dx, dx, fmaf(dy, dy, dz * dz)) + 1e-12f);
            float kern = erff(0.5f * r) * __fdividef(1.0f, r);
            acc += (j != il) ? qs[j] * kern : 0.0f;
        }
        e = 0.5f * qi * acc;
    }
    // block reduce (8 warps)
    __shared__ float wred[8];
    float v = e;
    v += __shfl_down_sync(0xffffffffu, v, 16);
    v += __shfl_down_sync(0xffffffffu, v, 8);
    v += __shfl_down_sync(0xffffffffu, v, 4);
    v += __shfl_down_sync(0xffffffffu, v, 2);
    v += __shfl_down_sync(0xffffffffu, v, 1);
    if ((threadIdx.x & 31) == 0) wred[threadIdx.x >> 5] = v;
    __syncthreads();
    if (threadIdx.x == 0) {
        float s = 0.0f;
#pragma unroll
        for (int w = 0; w < 8; w++) s += wred[w];
        atomicAdd(&out[OUT_TE + g], s);
    }
}

// ---------------- K7: total charge (warp-aggregated: batch is contiguous) ----
__global__ void k_total_charge(const int* __restrict__ batch, float* __restrict__ out) {
    int n = blockIdx.x * blockDim.x + threadIdx.x;
    if (n >= NN) return;
    float q = g_cd[n];
    int g = batch[n];
    // nodes are grouped by graph (1000 per graph): warp-reduce same-g runs
    int lane = threadIdx.x & 31;
    unsigned same = __match_any_sync(0xffffffffu, g);
    int leader = __ffs(same) - 1;
    for (int off = 16; off > 0; off >>= 1) {
        float o = __shfl_down_sync(0xffffffffu, q, off);
        int  og = __shfl_down_sync(0xffffffffu, g, off);
        if (lane + off < 32 && og == g) q += o;
    }
    if (lane == leader) atomicAdd(&out[OUT_TC + g], q);
}

// ---------------- K8: finalize total energy ----------------
__global__ void k_finalize(float* __restrict__ out) {
    int g = threadIdx.x;
    if (g < GG) {
        out[OUT_TE + g] += out[OUT_CONTRIB + g * 3 + 0]
                         + out[OUT_CONTRIB + g * 3 + 1]
                         + out[OUT_CONTRIB + g * 3 + 2];
    }
}

// ---------------- launch ----------------
extern "C" void kernel_launch(void* const* d_in, const int* in_sizes, int n_in,
                              void* d_out, int out_size) {
    const float* node_attrs = (const float*)d_in[0];   // [N,10]
    const float* positions  = (const float*)d_in[1];   // [N,3]
    const int*   edge_index = (const int*)d_in[2];     // [2,E]
    const int*   batch      = (const int*)d_in[3];     // [N]
    int p = (in_sizes[4] == NELS) ? 4 : 5;
    const float* atomic_energies = (const float*)d_in[p + 0];   // [10]
    const float* embed_w         = (const float*)d_in[p + 1];   // [10,64]
    const float* radial_w1       = (const float*)d_in[p + 2];   // [2,8,64]
    const float* radial_b1       = (const float*)d_in[p + 3];   // [2,64]
    const float* radial_w2       = (const float*)d_in[p + 4];   // [2,64,64]
    const float* prod_w          = (const float*)d_in[p + 5];   // [2,10,64]
    const float* readout_w       = (const float*)d_in[p + 6];   // [2,64]
    const float* ro2_w1          = (const float*)d_in[p + 7];   // [64,16]
    const float* ro2_b1          = (const float*)d_in[p + 8];   // [16]
    const float* ro2_w2          = (const float*)d_in[p + 9];   // [16]
    const float* charge_w        = (const float*)d_in[p + 10];  // [2,64]
    const float* flux_w          = (const float*)d_in[p + 11];  // [2,8]
    const float* formal_charges  = (const float*)d_in[p + 12];  // [10]
    float* out = (float*)d_out;

    k_zero<<<(NN * FF + 255) / 256, 256>>>(out);
    k_node_init<<<NN, 64>>>(node_attrs, positions, batch,
                            atomic_energies, embed_w, formal_charges, out);
    k_edge_geom<<<(EE + 255) / 256, 256>>>(positions, edge_index, batch, flux_w, out);

    for (int l = 0; l < 2; l++) {
        k_edge_mlp<<<1024, 256>>>(radial_w1 + l * NBB * FF,
                                  radial_b1 + l * FF,
                                  radial_w2 + l * FF * FF);
        k_node_update<<<NN, 64>>>(node_attrs, batch,
                                  prod_w + l * NELS * FF,
                                  charge_w + l * FF,
                                  readout_w + l * FF,
                                  ro2_w1, ro2_b1, ro2_w2,
                                  out, (l == 1) ? 1 : 0, l + 1);
    }

    k_coulomb<<<GG * 16, 256>>>(positions, out);
    k_total_charge<<<(NN + 255) / 256, 256>>>(batch, out);
    k_finalize<<<1, 32>>>(out);
}

// round 3
// speedup vs baseline: 2.2672x; 2.2672x over previous
#include <cuda_runtime.h>
#include <math.h>

#define NN   20000
#define FF   64
#define EE   320000
#define GG   20
#define NGG  1000
#define NELS 10
#define NBB  8
#define RMAXF 5.0f
#define HML  16

// output layout (float32, 20160 elems):
#define OUT_TE      0        // [20]  total_energy
#define OUT_NE      20       // [20000] node_energy
#define OUT_CONTRIB 20020    // [20,3] contributions
#define OUT_POL     20080    // [20,3] pol
#define OUT_TC      20140    // [20]  total_charge
#define OUT_TOTAL   20160

// ---------------- device scratch (no allocation allowed) ----------------
__device__ float g_sc[NN * FF];     // current node scalars
__device__ float g_agg[NN * FF];    // per-layer aggregation (s=0 only!)
__device__ float g_ef[EE * NBB];    // compacted active-edge radial features
__device__ int   g_asnd[EE];
__device__ int   g_arcv[EE];
__device__ float g_cd[NN];          // charge density
__device__ int   g_count;           // active edge count

// ---------------- K0: zero small accumulator regions ----------------
__global__ void k_zero(float* __restrict__ out) {
    int i = threadIdx.x;
    if (i < GG) out[OUT_TE + i] = 0.0f;                         // total_energy
    if (i < 140) out[OUT_CONTRIB + i] = 0.0f;                   // contrib+pol+tc
    if (i == 0) g_count = 0;
}

// ---------------- K1: node init (embed, E0, FQ, pol; 4 nodes/block) ---------
__global__ void __launch_bounds__(256)
k_node_init(const float* __restrict__ attrs,
            const float* __restrict__ pos,
            const int*   __restrict__ batch,
            const float* __restrict__ ae,
            const float* __restrict__ embw,
            const float* __restrict__ fc,
            float* __restrict__ out) {
    int lg = threadIdx.x >> 6;
    int f  = threadIdx.x & 63;
    int n  = blockIdx.x * 4 + lg;
    __shared__ float at[4][NELS];
    __shared__ float fqs[4];
    if (f < NELS) at[lg][f] = attrs[n * NELS + f];
    __syncthreads();
    float s = 0.0f;
#pragma unroll
    for (int k = 0; k < NELS; k++) s = fmaf(at[lg][k], embw[k * FF + f], s);
    g_sc[n * FF + f] = s;
    g_agg[n * FF + f] = 0.0f;
    if (f == 0) {
        float fq = 0.0f, ne0 = 0.0f;
#pragma unroll
        for (int k = 0; k < NELS; k++) { fq = fmaf(at[lg][k], fc[k], fq); ne0 = fmaf(at[lg][k], ae[k], ne0); }
        g_cd[n] = fq;
        out[OUT_NE + n] = ne0;
        atomicAdd(&out[OUT_CONTRIB + batch[n] * 3 + 0], ne0);
        fqs[lg] = fq;
    }
    __syncthreads();
    if (f < 3)
        atomicAdd(&out[OUT_POL + batch[n] * 3 + f], fqs[lg] * pos[n * 3 + f]);
}

// ---------------- K2: edge geometry + radial basis + flux/pol + compaction ---
// Warp-aggregated compaction; per-block smem aggregation of pol atomics.
__global__ void __launch_bounds__(256)
k_edge_geom(const float* __restrict__ pos,
            const int*   __restrict__ ei,
            const int*   __restrict__ batch,
            const float* __restrict__ fw,   // flux_w [2,8]
            float* __restrict__ out) {
    int e = blockIdx.x * 256 + threadIdx.x;    // grid sized exactly EE/256
    int lane = threadIdx.x & 31;
    __shared__ float polsm[GG * 3];
    if (threadIdx.x < GG * 3) polsm[threadIdx.x] = 0.0f;
    __syncthreads();

    int snd = ei[e], rcv = ei[EE + e];
    float dx = pos[rcv * 3 + 0] - pos[snd * 3 + 0];
    float dy = pos[rcv * 3 + 1] - pos[snd * 3 + 1];
    float dz = pos[rcv * 3 + 2] - pos[snd * 3 + 2];
    float r = sqrtf(fmaf(dx, dx, fmaf(dy, dy, dz * dz)) + 1e-12f);
    bool active = (r < RMAXF);
    float ef[NBB];
    float flux = 0.0f;
    if (active) {
        float x = r * (1.0f / RMAXF);
        float x2 = x * x;
        float x5 = x2 * x2 * x;
        float u = 1.0f + x5 * (-21.0f + x * (35.0f - 15.0f * x));
        float pref = 0.6324555320336759f * u / r;       // sqrt(2/5)*u/r
        float s1, c1;
        __sincosf(r * 0.6283185307179586f, &s1, &c1);   // pi/5 * r
        float sn = s1, cn = c1;
#pragma unroll
        for (int i = 0; i < NBB; i++) {
            float v = pref * sn;
            ef[i] = v;
            flux = fmaf(v, fw[i] + fw[NBB + i], flux);
            float sn2 = sn * c1 + cn * s1;
            cn = cn * c1 - sn * s1;
            sn = sn2;
        }
    }

    unsigned mask = __ballot_sync(0xffffffffu, active);
    if (mask) {
        int leader = __ffs(mask) - 1;
        int cnt = __popc(mask);
        int base = 0;
        if (lane == leader) base = atomicAdd(&g_count, cnt);
        base = __shfl_sync(0xffffffffu, base, leader);
        if (active) {
            int slot = base + __popc(mask & ((1u << lane) - 1u));
            float4* ef4 = (float4*)&g_ef[slot * NBB];
            ef4[0] = make_float4(ef[0], ef[1], ef[2], ef[3]);
            ef4[1] = make_float4(ef[4], ef[5], ef[6], ef[7]);
            g_asnd[slot] = snd;
            g_arcv[slot] = rcv;
            int g = batch[rcv];
            atomicAdd(&polsm[g * 3 + 0], flux * dx);
            atomicAdd(&polsm[g * 3 + 1], flux * dy);
            atomicAdd(&polsm[g * 3 + 2], flux * dz);
        }
    }
    __syncthreads();
    if (threadIdx.x < GG * 3) {
        float v = polsm[threadIdx.x];
        if (v != 0.0f) atomicAdd(&out[OUT_POL + threadIdx.x], v);
    }
}

// ---------------- K4: per-edge radial MLP + message scatter (s=0 only) -------
// Low-register design: W2 transposed in smem (float4 row stride 17 -> phase-
// conflict-free LDS.128); each 64-thread group does 8 edges per trip, one w
// load amortized over 8 edges; g_sc gather prefetched in phase 1.
__global__ void __launch_bounds__(256, 4)
k_edge_mlp(const float* __restrict__ W1,   // [8,64]
           const float* __restrict__ B1,   // [64]
           const float* __restrict__ W2) { // [64,64]
    __shared__ float4 w2t4[FF][17];        // w2t4[f][j4] = W2[4j4..4j4+3][f]
    __shared__ float4 hsm[4][8][16];       // [group][edge][j4]
    int tid = threadIdx.x;
    int f = tid & 63;
    int grp = tid >> 6;
    float* w2s = (float*)w2t4;             // row stride 68 floats
    for (int j = grp; j < FF; j += 4) w2s[f * 68 + j] = W2[j * FF + f];
    float w1r[NBB];
#pragma unroll
    for (int i = 0; i < NBB; i++) w1r[i] = W1[i * FF + f];
    float b1r = B1[f];
    __syncthreads();

    int count = g_count;
    for (int t = blockIdx.x * 32; t < count; t += gridDim.x * 32) {
        int base = t + grp * 8;
        float scv[8];
        // phase 1: hidden activations for 8 edges + prefetch sc[snd]
#pragma unroll
        for (int e = 0; e < 8; e++) {
            int slot = base + e;
            float h = 0.0f;
            scv[e] = 0.0f;
            if (slot < count) {
                int snd = __ldg(&g_asnd[slot]);
                scv[e] = __ldg(&g_sc[snd * FF + f]);
                const float4* ef4 = (const float4*)&g_ef[slot * NBB];
                float4 a = __ldg(ef4), b = __ldg(ef4 + 1);
                float acc = b1r;
                acc = fmaf(a.x, w1r[0], acc); acc = fmaf(a.y, w1r[1], acc);
                acc = fmaf(a.z, w1r[2], acc); acc = fmaf(a.w, w1r[3], acc);
                acc = fmaf(b.x, w1r[4], acc); acc = fmaf(b.y, w1r[5], acc);
                acc = fmaf(b.z, w1r[6], acc); acc = fmaf(b.w, w1r[7], acc);
                h = acc / (1.0f + __expf(-acc));     // silu
            }
            ((float*)&hsm[grp][e][0])[f] = h;
        }
        __syncthreads();
        // phase 2: R[e] = sum_j h[e][j] * W2[j][f]
        float R[8] = {0, 0, 0, 0, 0, 0, 0, 0};
#pragma unroll
        for (int j4 = 0; j4 < 16; j4++) {
            float4 w = w2t4[f][j4];                  // reused across 8 edges
#pragma unroll
            for (int e = 0; e < 8; e++) {
                float4 h4 = hsm[grp][e][j4];         // broadcast
                R[e] = fmaf(h4.x, w.x, R[e]); R[e] = fmaf(h4.y, w.y, R[e]);
                R[e] = fmaf(h4.z, w.z, R[e]); R[e] = fmaf(h4.w, w.w, R[e]);
            }
        }
        // phase 3: scatter messages
#pragma unroll
        for (int e = 0; e < 8; e++) {
            int slot = base + e;
            if (slot < count) {
                int rcv = __ldg(&g_arcv[slot]);
                atomicAdd(&g_agg[rcv * FF + f], R[e] * scv[e]);
            }
        }
        __syncthreads();
    }
}

// ---------------- K5: node update (4 nodes/block) ----------------
__global__ void __launch_bounds__(256)
k_node_update(const float* __restrict__ attrs,
              const int*   __restrict__ batch,
              const float* __restrict__ PW,    // prod_w[l]  [10,64]
              const float* __restrict__ CW,    // charge_w[l][64]
              const float* __restrict__ ROW,   // readout_w[l][64] (l==0)
              const float* __restrict__ RW1,   // ro2_w1 [64,16]
              const float* __restrict__ RB1,   // ro2_b1 [16]
              const float* __restrict__ RW2,   // ro2_w2 [16]
              float* __restrict__ out,
              int last, int cidx) {
    int lg = threadIdx.x >> 6;
    int f  = threadIdx.x & 63;
    int n  = blockIdx.x * 4 + lg;
    __shared__ float at[4][NELS];
    __shared__ float scsm[4][FF];
    __shared__ float red[4][FF];
    __shared__ float resc[4], rese[4];
    if (f < NELS) at[lg][f] = attrs[n * NELS + f];
    __syncthreads();
    float a = g_agg[n * FF + f] * 0.0625f;   // / AVG_NEIGH
    g_agg[n * FF + f] = 0.0f;                // pre-zero for next layer
    float pw = 0.0f;
#pragma unroll
    for (int k = 0; k < NELS; k++) pw = fmaf(at[lg][k], PW[k * FF + f], pw);
    float sc = fmaf(a, a, a) + g_sc[n * FF + f] * pw;
    g_sc[n * FF + f] = sc;
    scsm[lg][f] = sc;
    red[lg][f] = sc * CW[f];
    __syncthreads();
    if (f < 32) {          // group's f<32 = one full warp
        float v = red[lg][f] + red[lg][f + 32];
        v += __shfl_down_sync(0xffffffffu, v, 16);
        v += __shfl_down_sync(0xffffffffu, v, 8);
        v += __shfl_down_sync(0xffffffffu, v, 4);
        v += __shfl_down_sync(0xffffffffu, v, 2);
        v += __shfl_down_sync(0xffffffffu, v, 1);
        if (f == 0) resc[lg] = v;
    }
    __syncthreads();
    if (!last) {
        red[lg][f] = sc * ROW[f];
        __syncthreads();
        if (f < 32) {
            float v = red[lg][f] + red[lg][f + 32];
            v += __shfl_down_sync(0xffffffffu, v, 16);
            v += __shfl_down_sync(0xffffffffu, v, 8);
            v += __shfl_down_sync(0xffffffffu, v, 4);
            v += __shfl_down_sync(0xffffffffu, v, 2);
            v += __shfl_down_sync(0xffffffffu, v, 1);
            if (f == 0) rese[lg] = v;
        }
        __syncthreads();
    } else {
        if (f < HML) {
            float acc = RB1[f];
#pragma unroll
            for (int j = 0; j < FF; j++) acc = fmaf(scsm[lg][j], RW1[j * HML + f], acc);
            float hv = acc / (1.0f + __expf(-acc));
            red[lg][f] = hv * RW2[f];
        }
        __syncthreads();
        if (f == 0) {
            float v = 0.0f;
#pragma unroll
            for (int m = 0; m < HML; m++) v += red[lg][m];
            rese[lg] = v;
        }
        __syncthreads();
    }
    if (f == 0) {
        g_cd[n] += resc[lg];
        out[OUT_NE + n] += rese[lg];
        atomicAdd(&out[OUT_CONTRIB + batch[n] * 3 + cidx], rese[lg]);
    }
}

// ---------------- K6: screened Coulomb + total charge + finalize -------------
__global__ void __launch_bounds__(256)
k_coulomb(const float* __restrict__ pos, float* __restrict__ out) {
    int g = blockIdx.x >> 4;          // 16 blocks per graph
    int ipart = blockIdx.x & 15;
    __shared__ float qs[NGG], px[NGG], py[NGG], pz[NGG];
    int base = g * NGG;
    float qpart = 0.0f;
    for (int j = threadIdx.x; j < NGG; j += 256) {
        float q = g_cd[base + j];
        qs[j] = q;
        qpart += q;
        px[j] = pos[(base + j) * 3 + 0];
        py[j] = pos[(base + j) * 3 + 1];
        pz[j] = pos[(base + j) * 3 + 2];
    }
    __syncthreads();
    int il = ipart * 64 + (threadIdx.x & 63);
    int jc = threadIdx.x >> 6;        // 0..3
    float e = 0.0f;
    if (il < NGG) {
        float xi = px[il], yi = py[il], zi = pz[il], qi = qs[il];
        float acc = 0.0f;
        for (int j = jc; j < NGG; j += 4) {
            float dx = xi - px[j], dy = yi - py[j], dz = zi - pz[j];
            float r = sqrtf(fmaf(dx, dx, fmaf(dy, dy, dz * dz)) + 1e-12f);
            float kern = erff(0.5f * r) * __fdividef(1.0f, r);
            acc += (j != il) ? qs[j] * kern : 0.0f;
        }
        e = 0.5f * qi * acc;
    }
    // block reduce e (and qpart for ipart 0)
    __shared__ float wred[8], wq[8];
    float v = e, q = qpart;
    v += __shfl_down_sync(0xffffffffu, v, 16);
    q += __shfl_down_sync(0xffffffffu, q, 16);
    v += __shfl_down_sync(0xffffffffu, v, 8);
    q += __shfl_down_sync(0xffffffffu, q, 8);
    v += __shfl_down_sync(0xffffffffu, v, 4);
    q += __shfl_down_sync(0xffffffffu, q, 4);
    v += __shfl_down_sync(0xffffffffu, v, 2);
    q += __shfl_down_sync(0xffffffffu, q, 2);
    v += __shfl_down_sync(0xffffffffu, v, 1);
    q += __shfl_down_sync(0xffffffffu, q, 1);
    if ((threadIdx.x & 31) == 0) { wred[threadIdx.x >> 5] = v; wq[threadIdx.x >> 5] = q; }
    __syncthreads();
    if (threadIdx.x == 0) {
        float s = 0.0f, qsum = 0.0f;
#pragma unroll
        for (int w = 0; w < 8; w++) { s += wred[w]; qsum += wq[w]; }
        if (ipart == 0) {
            out[OUT_TC + g] = qsum;
            // fold contributions into total energy (contribs complete by now)
            s += out[OUT_CONTRIB + g * 3 + 0]
               + out[OUT_CONTRIB + g * 3 + 1]
               + out[OUT_CONTRIB + g * 3 + 2];
        }
        atomicAdd(&out[OUT_TE + g], s);
    }
}

// ---------------- launch ----------------
extern "C" void kernel_launch(void* const* d_in, const int* in_sizes, int n_in,
                              void* d_out, int out_size) {
    const float* node_attrs = (const float*)d_in[0];   // [N,10]
    const float* positions  = (const float*)d_in[1];   // [N,3]
    const int*   edge_index = (const int*)d_in[2];     // [2,E]
    const int*   batch      = (const int*)d_in[3];     // [N]
    int p = (in_sizes[4] == NELS) ? 4 : 5;
    const float* atomic_energies = (const float*)d_in[p + 0];   // [10]
    const float* embed_w         = (const float*)d_in[p + 1];   // [10,64]
    const float* radial_w1       = (const float*)d_in[p + 2];   // [2,8,64]
    const float* radial_b1       = (const float*)d_in[p + 3];   // [2,64]
    const float* radial_w2       = (const float*)d_in[p + 4];   // [2,64,64]
    const float* prod_w          = (const float*)d_in[p + 5];   // [2,10,64]
    const float* readout_w       = (const float*)d_in[p + 6];   // [2,64]
    const float* ro2_w1          = (const float*)d_in[p + 7];   // [64,16]
    const float* ro2_b1          = (const float*)d_in[p + 8];   // [16]
    const float* ro2_w2          = (const float*)d_in[p + 9];   // [16]
    const float* charge_w        = (const float*)d_in[p + 10];  // [2,64]
    const float* flux_w          = (const float*)d_in[p + 11];  // [2,8]
    const float* formal_charges  = (const float*)d_in[p + 12];  // [10]
    float* out = (float*)d_out;

    k_zero<<<1, 256>>>(out);
    k_node_init<<<NN / 4, 256>>>(node_attrs, positions, batch,
                                 atomic_energies, embed_w, formal_charges, out);
    k_edge_geom<<<EE / 256, 256>>>(positions, edge_index, batch, flux_w, out);

    for (int l = 0; l < 2; l++) {
        k_edge_mlp<<<592, 256>>>(radial_w1 + l * NBB * FF,
                                 radial_b1 + l * FF,
                                 radial_w2 + l * FF * FF);
        k_node_update<<<NN / 4, 256>>>(node_attrs, batch,
                                       prod_w + l * NELS * FF,
                                       charge_w + l * FF,
                                       readout_w + l * FF,
                                       ro2_w1, ro2_b1, ro2_w2,
                                       out, (l == 1) ? 1 : 0, l + 1);
    }

    k_coulomb<<<GG * 16, 256>>>(positions, out);
}

// round 4
// speedup vs baseline: 2.4052x; 1.0609x over previous
#include <cuda_runtime.h>
#include <math.h>

#define NN   20000
#define FF   64
#define EE   320000
#define GG   20
#define NGG  1000
#define NELS 10
#define NBB  8
#define RMAXF 5.0f
#define HML  16

// output layout (float32, 20160 elems):
#define OUT_TE      0        // [20]  total_energy
#define OUT_NE      20       // [20000] node_energy
#define OUT_CONTRIB 20020    // [20,3] contributions
#define OUT_POL     20080    // [20,3] pol
#define OUT_TC      20140    // [20]  total_charge
#define OUT_TOTAL   20160

// ---------------- device scratch (no allocation allowed) ----------------
__device__ float g_sc[NN * FF];     // current node scalars
__device__ float g_agg[NN * FF];    // per-layer aggregation (s=0 only!)
__device__ float g_ef[EE * NBB];    // compacted active-edge radial features
__device__ int   g_asnd[EE];
__device__ int   g_arcv[EE];
__device__ float g_cd[NN];          // charge density
__device__ int   g_count;           // active edge count

// ---------------- K0: zero small accumulator regions ----------------
__global__ void k_zero(float* __restrict__ out) {
    int i = threadIdx.x;
    if (i < GG) out[OUT_TE + i] = 0.0f;                         // total_energy
    if (i < 140) out[OUT_CONTRIB + i] = 0.0f;                   // contrib+pol+tc
    if (i == 0) g_count = 0;
}

// ---------------- K1: node init (embed, E0, FQ, pol; 4 nodes/block) ---------
__global__ void __launch_bounds__(256)
k_node_init(const float* __restrict__ attrs,
            const float* __restrict__ pos,
            const int*   __restrict__ batch,
            const float* __restrict__ ae,
            const float* __restrict__ embw,
            const float* __restrict__ fc,
            float* __restrict__ out) {
    int lg = threadIdx.x >> 6;
    int f  = threadIdx.x & 63;
    int n  = blockIdx.x * 4 + lg;
    __shared__ float at[4][NELS];
    __shared__ float fqs[4];
    if (f < NELS) at[lg][f] = attrs[n * NELS + f];
    __syncthreads();
    float s = 0.0f;
#pragma unroll
    for (int k = 0; k < NELS; k++) s = fmaf(at[lg][k], embw[k * FF + f], s);
    g_sc[n * FF + f] = s;
    g_agg[n * FF + f] = 0.0f;
    if (f == 0) {
        float fq = 0.0f, ne0 = 0.0f;
#pragma unroll
        for (int k = 0; k < NELS; k++) { fq = fmaf(at[lg][k], fc[k], fq); ne0 = fmaf(at[lg][k], ae[k], ne0); }
        g_cd[n] = fq;
        out[OUT_NE + n] = ne0;
        atomicAdd(&out[OUT_CONTRIB + batch[n] * 3 + 0], ne0);
        fqs[lg] = fq;
    }
    __syncthreads();
    if (f < 3)
        atomicAdd(&out[OUT_POL + batch[n] * 3 + f], fqs[lg] * pos[n * 3 + f]);
}

// ---------------- K2: edge geometry + radial basis + flux/pol + compaction ---
__global__ void __launch_bounds__(256)
k_edge_geom(const float* __restrict__ pos,
            const int*   __restrict__ ei,
            const int*   __restrict__ batch,
            const float* __restrict__ fw,   // flux_w [2,8]
            float* __restrict__ out) {
    int e = blockIdx.x * 256 + threadIdx.x;    // grid sized exactly EE/256
    int lane = threadIdx.x & 31;
    __shared__ float polsm[GG * 3];
    if (threadIdx.x < GG * 3) polsm[threadIdx.x] = 0.0f;
    __syncthreads();

    int snd = ei[e], rcv = ei[EE + e];
    float dx = pos[rcv * 3 + 0] - pos[snd * 3 + 0];
    float dy = pos[rcv * 3 + 1] - pos[snd * 3 + 1];
    float dz = pos[rcv * 3 + 2] - pos[snd * 3 + 2];
    float r = sqrtf(fmaf(dx, dx, fmaf(dy, dy, dz * dz)) + 1e-12f);
    bool active = (r < RMAXF);
    float ef[NBB];
    float flux = 0.0f;
    if (active) {
        float x = r * (1.0f / RMAXF);
        float x2 = x * x;
        float x5 = x2 * x2 * x;
        float u = 1.0f + x5 * (-21.0f + x * (35.0f - 15.0f * x));
        float pref = 0.6324555320336759f * u / r;       // sqrt(2/5)*u/r
        float s1, c1;
        __sincosf(r * 0.6283185307179586f, &s1, &c1);   // pi/5 * r
        float sn = s1, cn = c1;
#pragma unroll
        for (int i = 0; i < NBB; i++) {
            float v = pref * sn;
            ef[i] = v;
            flux = fmaf(v, fw[i] + fw[NBB + i], flux);
            float sn2 = sn * c1 + cn * s1;
            cn = cn * c1 - sn * s1;
            sn = sn2;
        }
    }

    unsigned mask = __ballot_sync(0xffffffffu, active);
    if (mask) {
        int leader = __ffs(mask) - 1;
        int cnt = __popc(mask);
        int base = 0;
        if (lane == leader) base = atomicAdd(&g_count, cnt);
        base = __shfl_sync(0xffffffffu, base, leader);
        if (active) {
            int slot = base + __popc(mask & ((1u << lane) - 1u));
            float4* ef4 = (float4*)&g_ef[slot * NBB];
            ef4[0] = make_float4(ef[0], ef[1], ef[2], ef[3]);
            ef4[1] = make_float4(ef[4], ef[5], ef[6], ef[7]);
            g_asnd[slot] = snd;
            g_arcv[slot] = rcv;
            int g = batch[rcv];
            atomicAdd(&polsm[g * 3 + 0], flux * dx);
            atomicAdd(&polsm[g * 3 + 1], flux * dy);
            atomicAdd(&polsm[g * 3 + 2], flux * dz);
        }
    }
    __syncthreads();
    if (threadIdx.x < GG * 3) {
        float v = polsm[threadIdx.x];
        if (v != 0.0f) atomicAdd(&out[OUT_POL + threadIdx.x], v);
    }
}

// ---------------- K4: per-edge radial MLP + message scatter (s=0 only) -------
// Warp-local design: each warp handles 8 edges/trip, each lane owns output
// features (lane, lane+32). h staged per-warp in smem, __syncwarp only (no
// block barriers). W2 transposed in smem, LDS amortized over 64 FMA per j4.
__global__ void __launch_bounds__(256, 3)
k_edge_mlp(const float* __restrict__ W1,   // [8,64]
           const float* __restrict__ B1,   // [64]
           const float* __restrict__ W2) { // [64,64]
    __shared__ float4 w2t4[FF][17];        // w2t4[f][j4] = W2[4j4..4j4+3][f]
    __shared__ float hsm[8][8][FF];        // [warp][edge][hidden]
    int tid = threadIdx.x;
    int warp = tid >> 5;
    int lane = tid & 31;
    int f0 = lane, f1 = lane + 32;

    {   // cooperative transpose of W2 into smem
        int fl = tid & 63;
        int q  = tid >> 6;
        float* w2s = (float*)w2t4;         // row stride 68 floats
        for (int j = q; j < FF; j += 4) w2s[fl * 68 + j] = W2[j * FF + fl];
    }
    float w1a[NBB], w1b[NBB];
#pragma unroll
    for (int i = 0; i < NBB; i++) { w1a[i] = W1[i * FF + f0]; w1b[i] = W1[i * FF + f1]; }
    float b1a = B1[f0], b1b = B1[f1];
    __syncthreads();

    int count = g_count;
    for (int t = blockIdx.x * 64; t < count; t += gridDim.x * 64) {
        int base = t + warp * 8;
        // phase 1: hidden activations (this lane's 2 hidden units) for 8 edges
#pragma unroll
        for (int e = 0; e < 8; e++) {
            int slot = base + e;
            float h0 = 0.0f, h1 = 0.0f;
            if (slot < count) {
                const float4* ef4 = (const float4*)&g_ef[slot * NBB];
                float4 a = __ldg(ef4), b = __ldg(ef4 + 1);
                float acc0 = b1a, acc1 = b1b;
                acc0 = fmaf(a.x, w1a[0], acc0); acc1 = fmaf(a.x, w1b[0], acc1);
                acc0 = fmaf(a.y, w1a[1], acc0); acc1 = fmaf(a.y, w1b[1], acc1);
                acc0 = fmaf(a.z, w1a[2], acc0); acc1 = fmaf(a.z, w1b[2], acc1);
                acc0 = fmaf(a.w, w1a[3], acc0); acc1 = fmaf(a.w, w1b[3], acc1);
                acc0 = fmaf(b.x, w1a[4], acc0); acc1 = fmaf(b.x, w1b[4], acc1);
                acc0 = fmaf(b.y, w1a[5], acc0); acc1 = fmaf(b.y, w1b[5], acc1);
                acc0 = fmaf(b.z, w1a[6], acc0); acc1 = fmaf(b.z, w1b[6], acc1);
                acc0 = fmaf(b.w, w1a[7], acc0); acc1 = fmaf(b.w, w1b[7], acc1);
                h0 = acc0 / (1.0f + __expf(-acc0));     // silu
                h1 = acc1 / (1.0f + __expf(-acc1));
            }
            hsm[warp][e][f0] = h0;
            hsm[warp][e][f1] = h1;
        }
        __syncwarp();
        // phase 2: R[f][e] = sum_j h[e][j] * W2[j][f] for f in {f0, f1}
        float R0[8] = {0, 0, 0, 0, 0, 0, 0, 0};
        float R1[8] = {0, 0, 0, 0, 0, 0, 0, 0};
#pragma unroll
        for (int j4 = 0; j4 < 16; j4++) {
            float4 wl = w2t4[f0][j4];
            float4 wh = w2t4[f1][j4];
#pragma unroll
            for (int e = 0; e < 8; e++) {
                float4 h4 = *(const float4*)&hsm[warp][e][j4 * 4];   // broadcast
                R0[e] = fmaf(h4.x, wl.x, R0[e]); R1[e] = fmaf(h4.x, wh.x, R1[e]);
                R0[e] = fmaf(h4.y, wl.y, R0[e]); R1[e] = fmaf(h4.y, wh.y, R1[e]);
                R0[e] = fmaf(h4.z, wl.z, R0[e]); R1[e] = fmaf(h4.z, wh.z, R1[e]);
                R0[e] = fmaf(h4.w, wl.w, R0[e]); R1[e] = fmaf(h4.w, wh.w, R1[e]);
            }
        }
        // phase 3: gather sc[snd], scatter messages to agg[rcv]
#pragma unroll
        for (int e = 0; e < 8; e++) {
            int slot = base + e;
            if (slot < count) {
                int snd = __ldg(&g_asnd[slot]);
                int rcv = __ldg(&g_arcv[slot]);
                float s0 = __ldg(&g_sc[snd * FF + f0]);
                float s1 = __ldg(&g_sc[snd * FF + f1]);
                atomicAdd(&g_agg[rcv * FF + f0], R0[e] * s0);
                atomicAdd(&g_agg[rcv * FF + f1], R1[e] * s1);
            }
        }
        __syncwarp();
    }
}

// ---------------- K5: node update (4 nodes/block) ----------------
__global__ void __launch_bounds__(256)
k_node_update(const float* __restrict__ attrs,
              const int*   __restrict__ batch,
              const float* __restrict__ PW,    // prod_w[l]  [10,64]
              const float* __restrict__ CW,    // charge_w[l][64]
              const float* __restrict__ ROW,   // readout_w[l][64] (l==0)
              const float* __restrict__ RW1,   // ro2_w1 [64,16]
              const float* __restrict__ RB1,   // ro2_b1 [16]
              const float* __restrict__ RW2,   // ro2_w2 [16]
              float* __restrict__ out,
              int last, int cidx) {
    int lg = threadIdx.x >> 6;
    int f  = threadIdx.x & 63;
    int n  = blockIdx.x * 4 + lg;
    __shared__ float at[4][NELS];
    __shared__ float scsm[4][FF];
    __shared__ float red[4][FF];
    __shared__ float resc[4], rese[4];
    if (f < NELS) at[lg][f] = attrs[n * NELS + f];
    __syncthreads();
    float a = g_agg[n * FF + f] * 0.0625f;   // / AVG_NEIGH
    g_agg[n * FF + f] = 0.0f;                // pre-zero for next layer
    float pw = 0.0f;
#pragma unroll
    for (int k = 0; k < NELS; k++) pw = fmaf(at[lg][k], PW[k * FF + f], pw);
    float sc = fmaf(a, a, a) + g_sc[n * FF + f] * pw;
    g_sc[n * FF + f] = sc;
    scsm[lg][f] = sc;
    red[lg][f] = sc * CW[f];
    __syncthreads();
    if (f < 32) {          // group's f<32 = one full warp
        float v = red[lg][f] + red[lg][f + 32];
        v += __shfl_down_sync(0xffffffffu, v, 16);
        v += __shfl_down_sync(0xffffffffu, v, 8);
        v += __shfl_down_sync(0xffffffffu, v, 4);
        v += __shfl_down_sync(0xffffffffu, v, 2);
        v += __shfl_down_sync(0xffffffffu, v, 1);
        if (f == 0) resc[lg] = v;
    }
    __syncthreads();
    if (!last) {
        red[lg][f] = sc * ROW[f];
        __syncthreads();
        if (f < 32) {
            float v = red[lg][f] + red[lg][f + 32];
            v += __shfl_down_sync(0xffffffffu, v, 16);
            v += __shfl_down_sync(0xffffffffu, v, 8);
            v += __shfl_down_sync(0xffffffffu, v, 4);
            v += __shfl_down_sync(0xffffffffu, v, 2);
            v += __shfl_down_sync(0xffffffffu, v, 1);
            if (f == 0) rese[lg] = v;
        }
        __syncthreads();
    } else {
        if (f < HML) {
            float acc = RB1[f];
#pragma unroll
            for (int j = 0; j < FF; j++) acc = fmaf(scsm[lg][j], RW1[j * HML + f], acc);
            float hv = acc / (1.0f + __expf(-acc));
            red[lg][f] = hv * RW2[f];
        }
        __syncthreads();
        if (f == 0) {
            float v = 0.0f;
#pragma unroll
            for (int m = 0; m < HML; m++) v += red[lg][m];
            rese[lg] = v;
        }
        __syncthreads();
    }
    if (f == 0) {
        g_cd[n] += resc[lg];
        out[OUT_NE + n] += rese[lg];
        atomicAdd(&out[OUT_CONTRIB + batch[n] * 3 + cidx], rese[lg]);
    }
}

// ---------------- K6: screened Coulomb + total charge + finalize -------------
__global__ void __launch_bounds__(256)
k_coulomb(const float* __restrict__ pos, float* __restrict__ out) {
    int g = blockIdx.x >> 4;          // 16 blocks per graph
    int ipart = blockIdx.x & 15;
    __shared__ float qs[NGG], px[NGG], py[NGG], pz[NGG];
    int base = g * NGG;
    float qpart = 0.0f;
    for (int j = threadIdx.x; j < NGG; j += 256) {
        float q = g_cd[base + j];
        qs[j] = q;
        qpart += q;
        px[j] = pos[(base + j) * 3 + 0];
        py[j] = pos[(base + j) * 3 + 1];
        pz[j] = pos[(base + j) * 3 + 2];
    }
    __syncthreads();
    int il = ipart * 64 + (threadIdx.x & 63);
    int jc = threadIdx.x >> 6;        // 0..3
    float e = 0.0f;
    if (il < NGG) {
        float xi = px[il], yi = py[il], zi = pz[il], qi = qs[il];
        float acc = 0.0f;
        for (int j = jc; j < NGG; j += 4) {
            float dx = xi - px[j], dy = yi - py[j], dz = zi - pz[j];
            float r = sqrtf(fmaf(dx, dx, fmaf(dy, dy, dz * dz)) + 1e-12f);
            float kern = erff(0.5f * r) * __fdividef(1.0f, r);
            acc += (j != il) ? qs[j] * kern : 0.0f;
        }
        e = 0.5f * qi * acc;
    }
    // block reduce e (and qpart for ipart 0)
    __shared__ float wred[8], wq[8];
    float v = e, q = qpart;
    v += __shfl_down_sync(0xffffffffu, v, 16);
    q += __shfl_down_sync(0xffffffffu, q, 16);
    v += __shfl_down_sync(0xffffffffu, v, 8);
    q += __shfl_down_sync(0xffffffffu, q, 8);
    v += __shfl_down_sync(0xffffffffu, v, 4);
    q += __shfl_down_sync(0xffffffffu, q, 4);
    v += __shfl_down_sync(0xffffffffu, v, 2);
    q += __shfl_down_sync(0xffffffffu, q, 2);
    v += __shfl_down_sync(0xffffffffu, v, 1);
    q += __shfl_down_sync(0xffffffffu, q, 1);
    if ((threadIdx.x & 31) == 0) { wred[threadIdx.x >> 5] = v; wq[threadIdx.x >> 5] = q; }
    __syncthreads();
    if (threadIdx.x == 0) {
        float s = 0.0f, qsum = 0.0f;
#pragma unroll
        for (int w = 0; w < 8; w++) { s += wred[w]; qsum += wq[w]; }
        if (ipart == 0) {
            out[OUT_TC + g] = qsum;
            s += out[OUT_CONTRIB + g * 3 + 0]
               + out[OUT_CONTRIB + g * 3 + 1]
               + out[OUT_CONTRIB + g * 3 + 2];
        }
        atomicAdd(&out[OUT_TE + g], s);
    }
}

// ---------------- launch ----------------
extern "C" void kernel_launch(void* const* d_in, const int* in_sizes, int n_in,
                              void* d_out, int out_size) {
    const float* node_attrs = (const float*)d_in[0];   // [N,10]
    const float* positions  = (const float*)d_in[1];   // [N,3]
    const int*   edge_index = (const int*)d_in[2];     // [2,E]
    const int*   batch      = (const int*)d_in[3];     // [N]
    int p = (in_sizes[4] == NELS) ? 4 : 5;
    const float* atomic_energies = (const float*)d_in[p + 0];   // [10]
    const float* embed_w         = (const float*)d_in[p + 1];   // [10,64]
    const float* radial_w1       = (const float*)d_in[p + 2];   // [2,8,64]
    const float* radial_b1       = (const float*)d_in[p + 3];   // [2,64]
    const float* radial_w2       = (const float*)d_in[p + 4];   // [2,64,64]
    const float* prod_w          = (const float*)d_in[p + 5];   // [2,10,64]
    const float* readout_w       = (const float*)d_in[p + 6];   // [2,64]
    const float* ro2_w1          = (const float*)d_in[p + 7];   // [64,16]
    const float* ro2_b1          = (const float*)d_in[p + 8];   // [16]
    const float* ro2_w2          = (const float*)d_in[p + 9];   // [16]
    const float* charge_w        = (const float*)d_in[p + 10];  // [2,64]
    const float* flux_w          = (const float*)d_in[p + 11];  // [2,8]
    const float* formal_charges  = (const float*)d_in[p + 12];  // [10]
    float* out = (float*)d_out;

    k_zero<<<1, 256>>>(out);
    k_node_init<<<NN / 4, 256>>>(node_attrs, positions, batch,
                                 atomic_energies, embed_w, formal_charges, out);
    k_edge_geom<<<EE / 256, 256>>>(positions, edge_index, batch, flux_w, out);

    for (int l = 0; l < 2; l++) {
        k_edge_mlp<<<444, 256>>>(radial_w1 + l * NBB * FF,
                                 radial_b1 + l * FF,
                                 radial_w2 + l * FF * FF);
        k_node_update<<<NN / 4, 256>>>(node_attrs, batch,
                                       prod_w + l * NELS * FF,
                                       charge_w + l * FF,
                                       readout_w + l * FF,
                                       ro2_w1, ro2_b1, ro2_w2,
                                       out, (l == 1) ? 1 : 0, l + 1);
    }

    k_coulomb<<<GG * 16, 256>>>(positions, out);
}

// round 5
// speedup vs baseline: 2.5531x; 1.0615x over previous
#include <cuda_runtime.h>
#include <math.h>

#define NN   20000
#define FF   64
#define EE   320000
#define GG   20
#define NGG  1000
#define NELS 10
#define NBB  8
#define RMAXF 5.0f
#define HML  16

// output layout (float32, 20160 elems):
#define OUT_TE      0        // [20]  total_energy
#define OUT_NE      20       // [20000] node_energy
#define OUT_CONTRIB 20020    // [20,3] contributions
#define OUT_POL     20080    // [20,3] pol
#define OUT_TC      20140    // [20]  total_charge
#define OUT_TOTAL   20160

// ---------------- device scratch (no allocation allowed) ----------------
__device__ float  g_sc[NN * FF];     // current node scalars
__device__ float  g_agg[NN * FF];    // per-layer aggregation (s=0 only!)
__device__ float  g_ef[EE * NBB];    // compacted active-edge radial features
__device__ int    g_asnd[EE];
__device__ int    g_arcv[EE];
__device__ float  g_cd[NN];          // charge density
__device__ float4 g_pos4[NN];        // padded positions (1-sector gathers)
__device__ int    g_count;           // active edge count

// ---------------- K0: zero small accumulator regions ----------------
__global__ void k_zero(float* __restrict__ out) {
    int i = threadIdx.x;
    if (i < GG) out[OUT_TE + i] = 0.0f;                         // total_energy
    if (i < 140) out[OUT_CONTRIB + i] = 0.0f;                   // contrib+pol+tc
    if (i == 0) g_count = 0;
}

// ---------------- K1: node init (embed, E0, FQ, pol, pos4; 4 nodes/block) ---
__global__ void __launch_bounds__(256)
k_node_init(const float* __restrict__ attrs,
            const float* __restrict__ pos,
            const int*   __restrict__ batch,
            const float* __restrict__ ae,
            const float* __restrict__ embw,
            const float* __restrict__ fc,
            float* __restrict__ out) {
    int lg = threadIdx.x >> 6;
    int f  = threadIdx.x & 63;
    int n  = blockIdx.x * 4 + lg;
    __shared__ float at[4][NELS];
    __shared__ float fqs[4];
    if (f < NELS) at[lg][f] = attrs[n * NELS + f];
    __syncthreads();
    float s = 0.0f;
#pragma unroll
    for (int k = 0; k < NELS; k++) s = fmaf(at[lg][k], embw[k * FF + f], s);
    g_sc[n * FF + f] = s;
    g_agg[n * FF + f] = 0.0f;
    if (f == 0) {
        float fq = 0.0f, ne0 = 0.0f;
#pragma unroll
        for (int k = 0; k < NELS; k++) { fq = fmaf(at[lg][k], fc[k], fq); ne0 = fmaf(at[lg][k], ae[k], ne0); }
        g_cd[n] = fq;
        out[OUT_NE + n] = ne0;
        atomicAdd(&out[OUT_CONTRIB + batch[n] * 3 + 0], ne0);
        fqs[lg] = fq;
        g_pos4[n] = make_float4(pos[n * 3 + 0], pos[n * 3 + 1], pos[n * 3 + 2], 0.0f);
    }
    __syncthreads();
    if (f < 3)
        atomicAdd(&out[OUT_POL + batch[n] * 3 + f], fqs[lg] * pos[n * 3 + f]);
}

// ---------------- K2: edge geometry + radial basis + flux/pol + compaction ---
__global__ void __launch_bounds__(256)
k_edge_geom(const int*   __restrict__ ei,
            const int*   __restrict__ batch,
            const float* __restrict__ fw,   // flux_w [2,8]
            float* __restrict__ out) {
    int e = blockIdx.x * 256 + threadIdx.x;    // grid sized exactly EE/256
    int lane = threadIdx.x & 31;
    __shared__ float polsm[GG * 3];
    if (threadIdx.x < GG * 3) polsm[threadIdx.x] = 0.0f;
    __syncthreads();

    int snd = ei[e], rcv = ei[EE + e];
    float4 ps = g_pos4[snd], pr = g_pos4[rcv];
    float dx = pr.x - ps.x, dy = pr.y - ps.y, dz = pr.z - ps.z;
    float d2 = fmaf(dx, dx, fmaf(dy, dy, dz * dz)) + 1e-12f;
    float rinv = rsqrtf(d2);
    float r = d2 * rinv;
    bool active = (r < RMAXF);
    float ef[NBB];
    float flux = 0.0f;
    if (active) {
        float x = r * (1.0f / RMAXF);
        float x2 = x * x;
        float x5 = x2 * x2 * x;
        float u = 1.0f + x5 * (-21.0f + x * (35.0f - 15.0f * x));
        float pref = 0.6324555320336759f * u * rinv;    // sqrt(2/5)*u/r
        float s1, c1;
        __sincosf(r * 0.6283185307179586f, &s1, &c1);   // pi/5 * r
        float sn = s1, cn = c1;
#pragma unroll
        for (int i = 0; i < NBB; i++) {
            float v = pref * sn;
            ef[i] = v;
            flux = fmaf(v, fw[i] + fw[NBB + i], flux);
            float sn2 = sn * c1 + cn * s1;
            cn = cn * c1 - sn * s1;
            sn = sn2;
        }
    }

    unsigned mask = __ballot_sync(0xffffffffu, active);
    if (mask) {
        int leader = __ffs(mask) - 1;
        int cnt = __popc(mask);
        int base = 0;
        if (lane == leader) base = atomicAdd(&g_count, cnt);
        base = __shfl_sync(0xffffffffu, base, leader);
        if (active) {
            int slot = base + __popc(mask & ((1u << lane) - 1u));
            float4* ef4 = (float4*)&g_ef[slot * NBB];
            ef4[0] = make_float4(ef[0], ef[1], ef[2], ef[3]);
            ef4[1] = make_float4(ef[4], ef[5], ef[6], ef[7]);
            g_asnd[slot] = snd;
            g_arcv[slot] = rcv;
            int g = batch[rcv];
            atomicAdd(&polsm[g * 3 + 0], flux * dx);
            atomicAdd(&polsm[g * 3 + 1], flux * dy);
            atomicAdd(&polsm[g * 3 + 2], flux * dz);
        }
    }
    __syncthreads();
    if (threadIdx.x < GG * 3) {
        float v = polsm[threadIdx.x];
        if (v != 0.0f) atomicAdd(&out[OUT_POL + threadIdx.x], v);
    }
}

// ---------------- K4: per-edge radial MLP + message scatter (s=0 only) -------
// Warp-local: 8 edges/trip/warp, each lane owns features (lane, lane+32).
// __syncwarp only; W2 transposed in smem (stride-17 float4 rows, phase-
// conflict-free); silu via MUFU (EX2 + RCP), no software fp32 div.
__global__ void __launch_bounds__(256, 3)
k_edge_mlp(const float* __restrict__ W1,   // [8,64]
           const float* __restrict__ B1,   // [64]
           const float* __restrict__ W2) { // [64,64]
    __shared__ float4 w2t4[FF][17];        // w2t4[f][j4] = W2[4j4..4j4+3][f]
    __shared__ float hsm[8][8][FF];        // [warp][edge][hidden]
    int tid = threadIdx.x;
    int warp = tid >> 5;
    int lane = tid & 31;
    int f0 = lane, f1 = lane + 32;

    {   // cooperative transpose of W2 into smem
        int fl = tid & 63;
        int q  = tid >> 6;
        float* w2s = (float*)w2t4;         // row stride 68 floats
        for (int j = q; j < FF; j += 4) w2s[fl * 68 + j] = W2[j * FF + fl];
    }
    float w1a[NBB], w1b[NBB];
#pragma unroll
    for (int i = 0; i < NBB; i++) { w1a[i] = W1[i * FF + f0]; w1b[i] = W1[i * FF + f1]; }
    float b1a = B1[f0], b1b = B1[f1];
    __syncthreads();

    int count = g_count;
    for (int t = blockIdx.x * 64; t < count; t += gridDim.x * 64) {
        int base = t + warp * 8;
        // phase 1: hidden activations (this lane's 2 hidden units) for 8 edges
#pragma unroll
        for (int e = 0; e < 8; e++) {
            int slot = base + e;
            float h0 = 0.0f, h1 = 0.0f;
            if (slot < count) {
                const float4* ef4 = (const float4*)&g_ef[slot * NBB];
                float4 a = __ldg(ef4), b = __ldg(ef4 + 1);
                float acc0 = b1a, acc1 = b1b;
                acc0 = fmaf(a.x, w1a[0], acc0); acc1 = fmaf(a.x, w1b[0], acc1);
                acc0 = fmaf(a.y, w1a[1], acc0); acc1 = fmaf(a.y, w1b[1], acc1);
                acc0 = fmaf(a.z, w1a[2], acc0); acc1 = fmaf(a.z, w1b[2], acc1);
                acc0 = fmaf(a.w, w1a[3], acc0); acc1 = fmaf(a.w, w1b[3], acc1);
                acc0 = fmaf(b.x, w1a[4], acc0); acc1 = fmaf(b.x, w1b[4], acc1);
                acc0 = fmaf(b.y, w1a[5], acc0); acc1 = fmaf(b.y, w1b[5], acc1);
                acc0 = fmaf(b.z, w1a[6], acc0); acc1 = fmaf(b.z, w1b[6], acc1);
                acc0 = fmaf(b.w, w1a[7], acc0); acc1 = fmaf(b.w, w1b[7], acc1);
                h0 = __fdividef(acc0, 1.0f + __expf(-acc0));     // silu (MUFU)
                h1 = __fdividef(acc1, 1.0f + __expf(-acc1));
            }
            hsm[warp][e][f0] = h0;
            hsm[warp][e][f1] = h1;
        }
        __syncwarp();
        // phase 2: R[f][e] = sum_j h[e][j] * W2[j][f] for f in {f0, f1}
        float R0[8] = {0, 0, 0, 0, 0, 0, 0, 0};
        float R1[8] = {0, 0, 0, 0, 0, 0, 0, 0};
#pragma unroll
        for (int j4 = 0; j4 < 16; j4++) {
            float4 wl = w2t4[f0][j4];
            float4 wh = w2t4[f1][j4];
#pragma unroll
            for (int e = 0; e < 8; e++) {
                float4 h4 = *(const float4*)&hsm[warp][e][j4 * 4];   // broadcast
                R0[e] = fmaf(h4.x, wl.x, R0[e]); R1[e] = fmaf(h4.x, wh.x, R1[e]);
                R0[e] = fmaf(h4.y, wl.y, R0[e]); R1[e] = fmaf(h4.y, wh.y, R1[e]);
                R0[e] = fmaf(h4.z, wl.z, R0[e]); R1[e] = fmaf(h4.z, wh.z, R1[e]);
                R0[e] = fmaf(h4.w, wl.w, R0[e]); R1[e] = fmaf(h4.w, wh.w, R1[e]);
            }
        }
        // phase 3: gather sc[snd], scatter messages to agg[rcv]
#pragma unroll
        for (int e = 0; e < 8; e++) {
            int slot = base + e;
            if (slot < count) {
                int snd = __ldg(&g_asnd[slot]);
                int rcv = __ldg(&g_arcv[slot]);
                float s0 = __ldg(&g_sc[snd * FF + f0]);
                float s1 = __ldg(&g_sc[snd * FF + f1]);
                atomicAdd(&g_agg[rcv * FF + f0], R0[e] * s0);
                atomicAdd(&g_agg[rcv * FF + f1], R1[e] * s1);
            }
        }
        __syncwarp();
    }
}

// ---------------- K5: node update (4 nodes/block) ----------------
__global__ void __launch_bounds__(256)
k_node_update(const float* __restrict__ attrs,
              const int*   __restrict__ batch,
              const float* __restrict__ PW,    // prod_w[l]  [10,64]
              const float* __restrict__ CW,    // charge_w[l][64]
              const float* __restrict__ ROW,   // readout_w[l][64] (l==0)
              const float* __restrict__ RW1,   // ro2_w1 [64,16]
              const float* __restrict__ RB1,   // ro2_b1 [16]
              const float* __restrict__ RW2,   // ro2_w2 [16]
              float* __restrict__ out,
              int last, int cidx) {
    int lg = threadIdx.x >> 6;
    int f  = threadIdx.x & 63;
    int n  = blockIdx.x * 4 + lg;
    __shared__ float at[4][NELS];
    __shared__ float scsm[4][FF];
    __shared__ float red[4][FF];
    __shared__ float resc[4], rese[4];
    if (f < NELS) at[lg][f] = attrs[n * NELS + f];
    __syncthreads();
    float a = g_agg[n * FF + f] * 0.0625f;   // / AVG_NEIGH
    g_agg[n * FF + f] = 0.0f;                // pre-zero for next layer
    float pw = 0.0f;
#pragma unroll
    for (int k = 0; k < NELS; k++) pw = fmaf(at[lg][k], PW[k * FF + f], pw);
    float sc = fmaf(a, a, a) + g_sc[n * FF + f] * pw;
    g_sc[n * FF + f] = sc;
    scsm[lg][f] = sc;
    red[lg][f] = sc * CW[f];
    __syncthreads();
    if (f < 32) {          // group's f<32 = one full warp
        float v = red[lg][f] + red[lg][f + 32];
        v += __shfl_down_sync(0xffffffffu, v, 16);
        v += __shfl_down_sync(0xffffffffu, v, 8);
        v += __shfl_down_sync(0xffffffffu, v, 4);
        v += __shfl_down_sync(0xffffffffu, v, 2);
        v += __shfl_down_sync(0xffffffffu, v, 1);
        if (f == 0) resc[lg] = v;
    }
    __syncthreads();
    if (!last) {
        red[lg][f] = sc * ROW[f];
        __syncthreads();
        if (f < 32) {
            float v = red[lg][f] + red[lg][f + 32];
            v += __shfl_down_sync(0xffffffffu, v, 16);
            v += __shfl_down_sync(0xffffffffu, v, 8);
            v += __shfl_down_sync(0xffffffffu, v, 4);
            v += __shfl_down_sync(0xffffffffu, v, 2);
            v += __shfl_down_sync(0xffffffffu, v, 1);
            if (f == 0) rese[lg] = v;
        }
        __syncthreads();
    } else {
        if (f < HML) {
            float acc = RB1[f];
#pragma unroll
            for (int j = 0; j < FF; j++) acc = fmaf(scsm[lg][j], RW1[j * HML + f], acc);
            float hv = __fdividef(acc, 1.0f + __expf(-acc));
            red[lg][f] = hv * RW2[f];
        }
        __syncthreads();
        if (f == 0) {
            float v = 0.0f;
#pragma unroll
            for (int m = 0; m < HML; m++) v += red[lg][m];
            rese[lg] = v;
        }
        __syncthreads();
    }
    if (f == 0) {
        g_cd[n] += resc[lg];
        out[OUT_NE + n] += rese[lg];
        atomicAdd(&out[OUT_CONTRIB + batch[n] * 3 + cidx], rese[lg]);
    }
}

// ---------------- K6: screened Coulomb + total charge + finalize -------------
__global__ void __launch_bounds__(256)
k_coulomb(float* __restrict__ out) {
    int g = blockIdx.x >> 4;          // 16 blocks per graph
    int ipart = blockIdx.x & 15;
    __shared__ float qs[NGG], px[NGG], py[NGG], pz[NGG];
    int base = g * NGG;
    float qpart = 0.0f;
    for (int j = threadIdx.x; j < NGG; j += 256) {
        float q = g_cd[base + j];
        qs[j] = q;
        qpart += q;
        float4 p4 = g_pos4[base + j];
        px[j] = p4.x; py[j] = p4.y; pz[j] = p4.z;
    }
    __syncthreads();
    int il = ipart * 64 + (threadIdx.x & 63);
    int jc = threadIdx.x >> 6;        // 0..3
    float e = 0.0f;
    if (il < NGG) {
        float xi = px[il], yi = py[il], zi = pz[il], qi = qs[il];
        float acc = 0.0f;
        for (int j = jc; j < NGG; j += 4) {
            float dx = xi - px[j], dy = yi - py[j], dz = zi - pz[j];
            float d2 = fmaf(dx, dx, fmaf(dy, dy, dz * dz)) + 1e-12f;
            float rinv = rsqrtf(d2);
            float r = d2 * rinv;
            float kern = erff(0.5f * r) * rinv;
            acc += (j != il) ? qs[j] * kern : 0.0f;
        }
        e = 0.5f * qi * acc;
    }
    // block reduce e (and qpart)
    __shared__ float wred[8], wq[8];
    float v = e, q = qpart;
    v += __shfl_down_sync(0xffffffffu, v, 16);
    q += __shfl_down_sync(0xffffffffu, q, 16);
    v += __shfl_down_sync(0xffffffffu, v, 8);
    q += __shfl_down_sync(0xffffffffu, q, 8);
    v += __shfl_down_sync(0xffffffffu, v, 4);
    q += __shfl_down_sync(0xffffffffu, q, 4);
    v += __shfl_down_sync(0xffffffffu, v, 2);
    q += __shfl_down_sync(0xffffffffu, q, 2);
    v += __shfl_down_sync(0xffffffffu, v, 1);
    q += __shfl_down_sync(0xffffffffu, q, 1);
    if ((threadIdx.x & 31) == 0) { wred[threadIdx.x >> 5] = v; wq[threadIdx.x >> 5] = q; }
    __syncthreads();
    if (threadIdx.x == 0) {
        float s = 0.0f, qsum = 0.0f;
#pragma unroll
        for (int w = 0; w < 8; w++) { s += wred[w]; qsum += wq[w]; }
        if (ipart == 0) {
            out[OUT_TC + g] = qsum;
            s += out[OUT_CONTRIB + g * 3 + 0]
               + out[OUT_CONTRIB + g * 3 + 1]
               + out[OUT_CONTRIB + g * 3 + 2];
        }
        atomicAdd(&out[OUT_TE + g], s);
    }
}

// ---------------- launch ----------------
extern "C" void kernel_launch(void* const* d_in, const int* in_sizes, int n_in,
                              void* d_out, int out_size) {
    const float* node_attrs = (const float*)d_in[0];   // [N,10]
    const float* positions  = (const float*)d_in[1];   // [N,3]
    const int*   edge_index = (const int*)d_in[2];     // [2,E]
    const int*   batch      = (const int*)d_in[3];     // [N]
    int p = (in_sizes[4] == NELS) ? 4 : 5;
    const float* atomic_energies = (const float*)d_in[p + 0];   // [10]
    const float* embed_w         = (const float*)d_in[p + 1];   // [10,64]
    const float* radial_w1       = (const float*)d_in[p + 2];   // [2,8,64]
    const float* radial_b1       = (const float*)d_in[p + 3];   // [2,64]
    const float* radial_w2       = (const float*)d_in[p + 4];   // [2,64,64]
    const float* prod_w          = (const float*)d_in[p + 5];   // [2,10,64]
    const float* readout_w       = (const float*)d_in[p + 6];   // [2,64]
    const float* ro2_w1          = (const float*)d_in[p + 7];   // [64,16]
    const float* ro2_b1          = (const float*)d_in[p + 8];   // [16]
    const float* ro2_w2          = (const float*)d_in[p + 9];   // [16]
    const float* charge_w        = (const float*)d_in[p + 10];  // [2,64]
    const float* flux_w          = (const float*)d_in[p + 11];  // [2,8]
    const float* formal_charges  = (const float*)d_in[p + 12];  // [10]
    float* out = (float*)d_out;

    k_zero<<<1, 256>>>(out);
    k_node_init<<<NN / 4, 256>>>(node_attrs, positions, batch,
                                 atomic_energies, embed_w, formal_charges, out);
    k_edge_geom<<<EE / 256, 256>>>(edge_index, batch, flux_w, out);

    for (int l = 0; l < 2; l++) {
        k_edge_mlp<<<444, 256>>>(radial_w1 + l * NBB * FF,
                                 radial_b1 + l * FF,
                                 radial_w2 + l * FF * FF);
        k_node_update<<<NN / 4, 256>>>(node_attrs, batch,
                                       prod_w + l * NELS * FF,
                                       charge_w + l * FF,
                                       readout_w + l * FF,
                                       ro2_w1, ro2_b1, ro2_w2,
                                       out, (l == 1) ? 1 : 0, l + 1);
    }

    k_coulomb<<<GG * 16, 256>>>(out);
}

// round 6
// speedup vs baseline: 2.7725x; 1.0860x over previous
#include <cuda_runtime.h>
#include <math.h>

#define NN   20000
#define FF   64
#define EE   320000
#define GG   20
#define NGG  1000
#define NELS 10
#define NBB  8
#define RMAXF 5.0f
#define HML  16

// output layout (float32, 20160 elems):
#define OUT_TE      0        // [20]  total_energy
#define OUT_NE      20       // [20000] node_energy
#define OUT_CONTRIB 20020    // [20,3] contributions
#define OUT_POL     20080    // [20,3] pol
#define OUT_TC      20140    // [20]  total_charge
#define OUT_TOTAL   20160

// ---------------- device scratch (no allocation allowed) ----------------
__device__ float  g_sc[NN * FF];     // current node scalars
__device__ float  g_agg[NN * FF];    // per-layer aggregation (s=0 only!)
__device__ float  g_ef[EE * NBB];    // compacted active-edge radial features
__device__ int2   g_aidx[EE];        // compacted (snd, rcv)
__device__ float  g_cd[NN];          // charge density
__device__ float4 g_pos4[NN];        // padded positions (1-sector gathers)
__device__ int    g_count;           // active edge count

// ---------------- PTX helpers ----------------
__device__ __forceinline__ unsigned smem_u32(const void* p) {
    return (unsigned)__cvta_generic_to_shared(p);
}
__device__ __forceinline__ void cp16(unsigned d, const void* g) {
    asm volatile("cp.async.ca.shared.global [%0], [%1], 16;" :: "r"(d), "l"(g));
}
__device__ __forceinline__ void cp8(unsigned d, const void* g) {
    asm volatile("cp.async.ca.shared.global [%0], [%1], 8;" :: "r"(d), "l"(g));
}
#define CP_COMMIT()  asm volatile("cp.async.commit_group;" ::: "memory")
#define CP_WAIT0()   asm volatile("cp.async.wait_group 0;" ::: "memory")

__device__ __forceinline__ unsigned long long pack2(float x, float y) {
    unsigned long long r;
    asm("mov.b64 %0, {%1, %2};" : "=l"(r) : "f"(x), "f"(y));
    return r;
}
__device__ __forceinline__ void ffma2(unsigned long long& d,
                                      unsigned long long a, unsigned long long b) {
    asm("fma.rn.f32x2 %0, %1, %2, %3;" : "=l"(d) : "l"(a), "l"(b), "l"(d));
}
__device__ __forceinline__ float2 unpack2(unsigned long long v) {
    float2 r;
    asm("mov.b64 {%0, %1}, %2;" : "=f"(r.x), "=f"(r.y) : "l"(v));
    return r;
}

// ---------------- K0: zero small accumulator regions ----------------
__global__ void k_zero(float* __restrict__ out) {
    int i = threadIdx.x;
    if (i < GG) out[OUT_TE + i] = 0.0f;                         // total_energy
    if (i < 140) out[OUT_CONTRIB + i] = 0.0f;                   // contrib+pol+tc
    if (i == 0) g_count = 0;
}

// ---------------- K1: node init (embed, E0, FQ, pol, pos4; 4 nodes/block) ---
__global__ void __launch_bounds__(256)
k_node_init(const float* __restrict__ attrs,
            const float* __restrict__ pos,
            const int*   __restrict__ batch,
            const float* __restrict__ ae,
            const float* __restrict__ embw,
            const float* __restrict__ fc,
            float* __restrict__ out) {
    int lg = threadIdx.x >> 6;
    int f  = threadIdx.x & 63;
    int n  = blockIdx.x * 4 + lg;
    __shared__ float at[4][NELS];
    __shared__ float fqs[4];
    if (f < NELS) at[lg][f] = attrs[n * NELS + f];
    __syncthreads();
    float s = 0.0f;
#pragma unroll
    for (int k = 0; k < NELS; k++) s = fmaf(at[lg][k], embw[k * FF + f], s);
    g_sc[n * FF + f] = s;
    g_agg[n * FF + f] = 0.0f;
    if (f == 0) {
        float fq = 0.0f, ne0 = 0.0f;
#pragma unroll
        for (int k = 0; k < NELS; k++) { fq = fmaf(at[lg][k], fc[k], fq); ne0 = fmaf(at[lg][k], ae[k], ne0); }
        g_cd[n] = fq;
        out[OUT_NE + n] = ne0;
        atomicAdd(&out[OUT_CONTRIB + batch[n] * 3 + 0], ne0);
        fqs[lg] = fq;
        g_pos4[n] = make_float4(pos[n * 3 + 0], pos[n * 3 + 1], pos[n * 3 + 2], 0.0f);
    }
    __syncthreads();
    if (f < 3)
        atomicAdd(&out[OUT_POL + batch[n] * 3 + f], fqs[lg] * pos[n * 3 + f]);
}

// ---------------- K2: edge geometry + radial basis + flux/pol + compaction ---
__global__ void __launch_bounds__(256)
k_edge_geom(const int*   __restrict__ ei,
            const int*   __restrict__ batch,
            const float* __restrict__ fw,   // flux_w [2,8]
            float* __restrict__ out) {
    int e = blockIdx.x * 256 + threadIdx.x;    // grid sized exactly EE/256
    int lane = threadIdx.x & 31;
    __shared__ float polsm[GG * 3];
    if (threadIdx.x < GG * 3) polsm[threadIdx.x] = 0.0f;
    __syncthreads();

    int snd = ei[e], rcv = ei[EE + e];
    float4 ps = g_pos4[snd], pr = g_pos4[rcv];
    float dx = pr.x - ps.x, dy = pr.y - ps.y, dz = pr.z - ps.z;
    float d2 = fmaf(dx, dx, fmaf(dy, dy, dz * dz)) + 1e-12f;
    float rinv = rsqrtf(d2);
    float r = d2 * rinv;
    bool active = (r < RMAXF);
    float ef[NBB];
    float flux = 0.0f;
    if (active) {
        float x = r * (1.0f / RMAXF);
        float x2 = x * x;
        float x5 = x2 * x2 * x;
        float u = 1.0f + x5 * (-21.0f + x * (35.0f - 15.0f * x));
        float pref = 0.6324555320336759f * u * rinv;    // sqrt(2/5)*u/r
        float s1, c1;
        __sincosf(r * 0.6283185307179586f, &s1, &c1);   // pi/5 * r
        float sn = s1, cn = c1;
#pragma unroll
        for (int i = 0; i < NBB; i++) {
            float v = pref * sn;
            ef[i] = v;
            flux = fmaf(v, fw[i] + fw[NBB + i], flux);
            float sn2 = sn * c1 + cn * s1;
            cn = cn * c1 - sn * s1;
            sn = sn2;
        }
    }

    unsigned mask = __ballot_sync(0xffffffffu, active);
    if (mask) {
        int leader = __ffs(mask) - 1;
        int cnt = __popc(mask);
        int base = 0;
        if (lane == leader) base = atomicAdd(&g_count, cnt);
        base = __shfl_sync(0xffffffffu, base, leader);
        if (active) {
            int slot = base + __popc(mask & ((1u << lane) - 1u));
            float4* ef4 = (float4*)&g_ef[slot * NBB];
            ef4[0] = make_float4(ef[0], ef[1], ef[2], ef[3]);
            ef4[1] = make_float4(ef[4], ef[5], ef[6], ef[7]);
            g_aidx[slot] = make_int2(snd, rcv);
            int g = batch[rcv];
            atomicAdd(&polsm[g * 3 + 0], flux * dx);
            atomicAdd(&polsm[g * 3 + 1], flux * dy);
            atomicAdd(&polsm[g * 3 + 2], flux * dz);
        }
    }
    __syncthreads();
    if (threadIdx.x < GG * 3) {
        float v = polsm[threadIdx.x];
        if (v != 0.0f) atomicAdd(&out[OUT_POL + threadIdx.x], v);
    }
}

// ---------------- K4: per-edge radial MLP + message scatter (s=0 only) -------
// Warp-local, 8 edges/trip/warp, 2 features/lane (f0=lane, f1=lane+32).
// cp.async double-buffered prefetch of ef + idx; phase2 uses fma.rn.f32x2
// over edge pairs (acc = (R[2e], R[2e+1])).
__global__ void __launch_bounds__(256, 3)
k_edge_mlp(const float* __restrict__ W1,   // [8,64]
           const float* __restrict__ B1,   // [64]
           const float* __restrict__ W2) { // [64,64]
    __shared__ float4 w2t4[FF][17];        // w2t4[f][j4] = W2[4j4..4j4+3][f]
    __shared__ float2 hp[8][4][FF];        // [warp][edge-pair][hidden j]
    __shared__ float4 efb[2][8][8][2];     // [stage][warp][edge][2xfloat4]
    __shared__ int2   idb[2][8][8];        // [stage][warp][edge]
    int tid = threadIdx.x;
    int warp = tid >> 5;
    int lane = tid & 31;
    int f0 = lane, f1 = lane + 32;

    {   // cooperative transpose of W2 into smem
        int fl = tid & 63;
        int q  = tid >> 6;
        float* w2s = (float*)w2t4;         // row stride 68 floats
        for (int j = q; j < FF; j += 4) w2s[fl * 68 + j] = W2[j * FF + fl];
    }
    float w1a[NBB], w1b[NBB];
#pragma unroll
    for (int i = 0; i < NBB; i++) { w1a[i] = W1[i * FF + f0]; w1b[i] = W1[i * FF + f1]; }
    float b1a = B1[f0], b1b = B1[f1];
    __syncthreads();

    int count = g_count;
    int stride = gridDim.x * 64;

    // prologue: prefetch trip 0 into stage 0
    {
        int slot = blockIdx.x * 64 + warp * 8 + lane;
        if (lane < 8 && slot < count) {
            cp16(smem_u32(&efb[0][warp][lane][0]), &g_ef[slot * NBB]);
            cp16(smem_u32(&efb[0][warp][lane][1]), &g_ef[slot * NBB + 4]);
            cp8(smem_u32(&idb[0][warp][lane]), &g_aidx[slot]);
        }
        CP_COMMIT();
    }

    int s = 0;
    for (int tb = blockIdx.x * 64; tb < count; tb += stride) {
        int base = tb + warp * 8;
        CP_WAIT0();
        __syncwarp();
        // prefetch next trip into the other stage
        {
            int slot = tb + stride + warp * 8 + lane;
            if (lane < 8 && slot < count) {
                cp16(smem_u32(&efb[s ^ 1][warp][lane][0]), &g_ef[slot * NBB]);
                cp16(smem_u32(&efb[s ^ 1][warp][lane][1]), &g_ef[slot * NBB + 4]);
                cp8(smem_u32(&idb[s ^ 1][warp][lane]), &g_aidx[slot]);
            }
            CP_COMMIT();
        }
        // phase 1: hidden activations for 8 edges (this lane's 2 hidden units)
#pragma unroll
        for (int e = 0; e < 8; e++) {
            int slot = base + e;
            float h0 = 0.0f, h1 = 0.0f;
            if (slot < count) {
                float4 a = efb[s][warp][e][0];
                float4 b = efb[s][warp][e][1];
                float acc0 = b1a, acc1 = b1b;
                acc0 = fmaf(a.x, w1a[0], acc0); acc1 = fmaf(a.x, w1b[0], acc1);
                acc0 = fmaf(a.y, w1a[1], acc0); acc1 = fmaf(a.y, w1b[1], acc1);
                acc0 = fmaf(a.z, w1a[2], acc0); acc1 = fmaf(a.z, w1b[2], acc1);
                acc0 = fmaf(a.w, w1a[3], acc0); acc1 = fmaf(a.w, w1b[3], acc1);
                acc0 = fmaf(b.x, w1a[4], acc0); acc1 = fmaf(b.x, w1b[4], acc1);
                acc0 = fmaf(b.y, w1a[5], acc0); acc1 = fmaf(b.y, w1b[5], acc1);
                acc0 = fmaf(b.z, w1a[6], acc0); acc1 = fmaf(b.z, w1b[6], acc1);
                acc0 = fmaf(b.w, w1a[7], acc0); acc1 = fmaf(b.w, w1b[7], acc1);
                h0 = __fdividef(acc0, 1.0f + __expf(-acc0));     // silu (MUFU)
                h1 = __fdividef(acc1, 1.0f + __expf(-acc1));
            }
            ((float*)&hp[warp][e >> 1][f0])[e & 1] = h0;
            ((float*)&hp[warp][e >> 1][f1])[e & 1] = h1;
        }
        __syncwarp();
        // phase 2: packed f32x2 GEMM: acc0[ep] = (R[2ep][f0], R[2ep+1][f0]) etc.
        unsigned long long A0[4], A1[4];
#pragma unroll
        for (int ep = 0; ep < 4; ep++) { A0[ep] = 0ull; A1[ep] = 0ull; }
#pragma unroll
        for (int j4 = 0; j4 < 16; j4++) {
            float4 wl4 = w2t4[f0][j4];
            float4 wh4 = w2t4[f1][j4];
            float wls[4] = {wl4.x, wl4.y, wl4.z, wl4.w};
            float whs[4] = {wh4.x, wh4.y, wh4.z, wh4.w};
#pragma unroll
            for (int jj = 0; jj < 4; jj++) {
                int j = j4 * 4 + jj;
                unsigned long long pwl = pack2(wls[jj], wls[jj]);
                unsigned long long pwh = pack2(whs[jj], whs[jj]);
#pragma unroll
                for (int ep = 0; ep < 4; ep++) {
                    unsigned long long h2 =
                        *(const unsigned long long*)&hp[warp][ep][j];  // broadcast
                    ffma2(A0[ep], h2, pwl);
                    ffma2(A1[ep], h2, pwh);
                }
            }
        }
        // phase 3: gather sc[snd], scatter messages to agg[rcv]
#pragma unroll
        for (int ep = 0; ep < 4; ep++) {
            float2 R0 = unpack2(A0[ep]);
            float2 R1 = unpack2(A1[ep]);
#pragma unroll
            for (int h = 0; h < 2; h++) {
                int slot = base + ep * 2 + h;
                if (slot < count) {
                    int2 sr = idb[s][warp][ep * 2 + h];
                    float r0 = h ? R0.y : R0.x;
                    float r1 = h ? R1.y : R1.x;
                    float s0 = __ldg(&g_sc[sr.x * FF + f0]);
                    float s1 = __ldg(&g_sc[sr.x * FF + f1]);
                    atomicAdd(&g_agg[sr.y * FF + f0], r0 * s0);
                    atomicAdd(&g_agg[sr.y * FF + f1], r1 * s1);
                }
            }
        }
        __syncwarp();
        s ^= 1;
    }
    CP_WAIT0();
}

// ---------------- K5: node update (4 nodes/block) ----------------
__global__ void __launch_bounds__(256)
k_node_update(const float* __restrict__ attrs,
              const int*   __restrict__ batch,
              const float* __restrict__ PW,    // prod_w[l]  [10,64]
              const float* __restrict__ CW,    // charge_w[l][64]
              const float* __restrict__ ROW,   // readout_w[l][64] (l==0)
              const float* __restrict__ RW1,   // ro2_w1 [64,16]
              const float* __restrict__ RB1,   // ro2_b1 [16]
              const float* __restrict__ RW2,   // ro2_w2 [16]
              float* __restrict__ out,
              int last, int cidx) {
    int lg = threadIdx.x >> 6;
    int f  = threadIdx.x & 63;
    int n  = blockIdx.x * 4 + lg;
    __shared__ float at[4][NELS];
    __shared__ float scsm[4][FF];
    __shared__ float red[4][FF];
    __shared__ float resc[4], rese[4];
    if (f < NELS) at[lg][f] = attrs[n * NELS + f];
    __syncthreads();
    float a = g_agg[n * FF + f] * 0.0625f;   // / AVG_NEIGH
    g_agg[n * FF + f] = 0.0f;                // pre-zero for next layer
    float pw = 0.0f;
#pragma unroll
    for (int k = 0; k < NELS; k++) pw = fmaf(at[lg][k], PW[k * FF + f], pw);
    float sc = fmaf(a, a, a) + g_sc[n * FF + f] * pw;
    g_sc[n * FF + f] = sc;
    scsm[lg][f] = sc;
    red[lg][f] = sc * CW[f];
    __syncthreads();
    if (f < 32) {          // group's f<32 = one full warp
        float v = red[lg][f] + red[lg][f + 32];
        v += __shfl_down_sync(0xffffffffu, v, 16);
        v += __shfl_down_sync(0xffffffffu, v, 8);
        v += __shfl_down_sync(0xffffffffu, v, 4);
        v += __shfl_down_sync(0xffffffffu, v, 2);
        v += __shfl_down_sync(0xffffffffu, v, 1);
        if (f == 0) resc[lg] = v;
    }
    __syncthreads();
    if (!last) {
        red[lg][f] = sc * ROW[f];
        __syncthreads();
        if (f < 32) {
            float v = red[lg][f] + red[lg][f + 32];
            v += __shfl_down_sync(0xffffffffu, v, 16);
            v += __shfl_down_sync(0xffffffffu, v, 8);
            v += __shfl_down_sync(0xffffffffu, v, 4);
            v += __shfl_down_sync(0xffffffffu, v, 2);
            v += __shfl_down_sync(0xffffffffu, v, 1);
            if (f == 0) rese[lg] = v;
        }
        __syncthreads();
    } else {
        if (f < HML) {
            float acc = RB1[f];
#pragma unroll
            for (int j = 0; j < FF; j++) acc = fmaf(scsm[lg][j], RW1[j * HML + f], acc);
            float hv = __fdividef(acc, 1.0f + __expf(-acc));
            red[lg][f] = hv * RW2[f];
        }
        __syncthreads();
        if (f == 0) {
            float v = 0.0f;
#pragma unroll
            for (int m = 0; m < HML; m++) v += red[lg][m];
            rese[lg] = v;
        }
        __syncthreads();
    }
    if (f == 0) {
        g_cd[n] += resc[lg];
        out[OUT_NE + n] += rese[lg];
        atomicAdd(&out[OUT_CONTRIB + batch[n] * 3 + cidx], rese[lg]);
    }
}

// ---------------- K6: screened Coulomb + total charge + finalize -------------
__global__ void __launch_bounds__(256)
k_coulomb(float* __restrict__ out) {
    int g = blockIdx.x >> 4;          // 16 blocks per graph
    int ipart = blockIdx.x & 15;
    __shared__ float qs[NGG], px[NGG], py[NGG], pz[NGG];
    int base = g * NGG;
    float qpart = 0.0f;
    for (int j = threadIdx.x; j < NGG; j += 256) {
        float q = g_cd[base + j];
        qs[j] = q;
        qpart += q;
        float4 p4 = g_pos4[base + j];
        px[j] = p4.x; py[j] = p4.y; pz[j] = p4.z;
    }
    __syncthreads();
    int il = ipart * 64 + (threadIdx.x & 63);
    int jc = threadIdx.x >> 6;        // 0..3
    float e = 0.0f;
    if (il < NGG) {
        float xi = px[il], yi = py[il], zi = pz[il], qi = qs[il];
        float acc0 = 0.0f, acc1 = 0.0f;
        // NGG = 1000 = 8 * 125: dual-accumulator, unconditional FMA
        for (int j = jc; j < NGG; j += 8) {
            {
                float dx = xi - px[j], dy = yi - py[j], dz = zi - pz[j];
                float d2 = fmaf(dx, dx, fmaf(dy, dy, dz * dz)) + 1e-12f;
                float rinv = rsqrtf(d2);
                float r = d2 * rinv;
                acc0 = fmaf(qs[j], erff(0.5f * r) * rinv, acc0);
            }
            {
                int j2 = j + 4;
                float dx = xi - px[j2], dy = yi - py[j2], dz = zi - pz[j2];
                float d2 = fmaf(dx, dx, fmaf(dy, dy, dz * dz)) + 1e-12f;
                float rinv = rsqrtf(d2);
                float r = d2 * rinv;
                acc1 = fmaf(qs[j2], erff(0.5f * r) * rinv, acc1);
            }
        }
        float acc = acc0 + acc1;
        if ((il & 3) == jc) {
            // subtract self term computed the same way (d2 = 1e-12)
            float rinv = rsqrtf(1e-12f);
            float r = 1e-12f * rinv;
            acc -= qi * erff(0.5f * r) * rinv;
        }
        e = 0.5f * qi * acc;
    }
    // block reduce e (and qpart)
    __shared__ float wred[8], wq[8];
    float v = e, q = qpart;
    v += __shfl_down_sync(0xffffffffu, v, 16);
    q += __shfl_down_sync(0xffffffffu, q, 16);
    v += __shfl_down_sync(0xffffffffu, v, 8);
    q += __shfl_down_sync(0xffffffffu, q, 8);
    v += __shfl_down_sync(0xffffffffu, v, 4);
    q += __shfl_down_sync(0xffffffffu, q, 4);
    v += __shfl_down_sync(0xffffffffu, v, 2);
    q += __shfl_down_sync(0xffffffffu, q, 2);
    v += __shfl_down_sync(0xffffffffu, v, 1);
    q += __shfl_down_sync(0xffffffffu, q, 1);
    if ((threadIdx.x & 31) == 0) { wred[threadIdx.x >> 5] = v; wq[threadIdx.x >> 5] = q; }
    __syncthreads();
    if (threadIdx.x == 0) {
        float s = 0.0f, qsum = 0.0f;
#pragma unroll
        for (int w = 0; w < 8; w++) { s += wred[w]; qsum += wq[w]; }
        if (ipart == 0) {
            out[OUT_TC + g] = qsum;
            s += out[OUT_CONTRIB + g * 3 + 0]
               + out[OUT_CONTRIB + g * 3 + 1]
               + out[OUT_CONTRIB + g * 3 + 2];
        }
        atomicAdd(&out[OUT_TE + g], s);
    }
}

// ---------------- launch ----------------
extern "C" void kernel_launch(void* const* d_in, const int* in_sizes, int n_in,
                              void* d_out, int out_size) {
    const float* node_attrs = (const float*)d_in[0];   // [N,10]
    const float* positions  = (const float*)d_in[1];   // [N,3]
    const int*   edge_index = (const int*)d_in[2];     // [2,E]
    const int*   batch      = (const int*)d_in[3];     // [N]
    int p = (in_sizes[4] == NELS) ? 4 : 5;
    const float* atomic_energies = (const float*)d_in[p + 0];   // [10]
    const float* embed_w         = (const float*)d_in[p + 1];   // [10,64]
    const float* radial_w1       = (const float*)d_in[p + 2];   // [2,8,64]
    const float* radial_b1       = (const float*)d_in[p + 3];   // [2,64]
    const float* radial_w2       = (const float*)d_in[p + 4];   // [2,64,64]
    const float* prod_w          = (const float*)d_in[p + 5];   // [2,10,64]
    const float* readout_w       = (const float*)d_in[p + 6];   // [2,64]
    const float* ro2_w1          = (const float*)d_in[p + 7];   // [64,16]
    const float* ro2_b1          = (const float*)d_in[p + 8];   // [16]
    const float* ro2_w2          = (const float*)d_in[p + 9];   // [16]
    const float* charge_w        = (const float*)d_in[p + 10];  // [2,64]
    const float* flux_w          = (const float*)d_in[p + 11];  // [2,8]
    const float* formal_charges  = (const float*)d_in[p + 12];  // [10]
    float* out = (float*)d_out;

    k_zero<<<1, 256>>>(out);
    k_node_init<<<NN / 4, 256>>>(node_attrs, positions, batch,
                                 atomic_energies, embed_w, formal_charges, out);
    k_edge_geom<<<EE / 256, 256>>>(edge_index, batch, flux_w, out);

    for (int l = 0; l < 2; l++) {
        k_edge_mlp<<<444, 256>>>(radial_w1 + l * NBB * FF,
                                 radial_b1 + l * FF,
                                 radial_w2 + l * FF * FF);
        k_node_update<<<NN / 4, 256>>>(node_attrs, batch,
                                       prod_w + l * NELS * FF,
                                       charge_w + l * FF,
                                       readout_w + l * FF,
                                       ro2_w1, ro2_b1, ro2_w2,
                                       out, (l == 1) ? 1 : 0, l + 1);
    }

    k_coulomb<<<GG * 16, 256>>>(out);
}